// round 6
// baseline (speedup 1.0000x reference)
#include <cuda_runtime.h>
#include <cuda_bf16.h>
#include <math.h>

// Problem constants (fixed shapes)
#define NN      20000
#define LATENT  512
#define HID     256
#define OUTC    128
#define HEADS   2
#define FEAT    (HEADS*OUTC)   // 256
#define NEG_SLOPE 0.2f

// ---------------- scratch (static device globals; 16B aligned for float4) ---
__device__ __align__(16) float g_x1[NN * HID];          // relu(z@W1+b1)   [20000,256]
__device__ __align__(16) float g_x2[NN * (HID*HEADS)];  // relu(x1@W2+b2)  [20000,512]
__device__ __align__(16) float g_xp[NN * FEAT];         // x2@Wg           [20000,256]
__device__ __align__(16) float g_asrc[NN * HEADS];
__device__ __align__(16) float g_adst[NN * HEADS];
__device__ __align__(16) float g_amax[NN * HEADS];
__device__ __align__(16) float g_denom[NN * HEADS];
__device__ __align__(16) float g_accum[NN * FEAT];      // unnormalized msg sum

// edge_index dtype flag: 1 = int64, 0 = int32. Monotonic (only ever set to 0),
// so deterministic across graph replays.
__device__ int g_is64 = 1;

// Device-side buffer selector (avoids cudaGetSymbolAddress entirely)
__device__ __forceinline__ float* buf_sel(int id) {
    switch (id) {
        case 1: return g_x1;
        case 2: return g_x2;
        case 3: return g_xp;
        case 4: return g_accum;
    }
    return nullptr;
}

// ---------------- helpers ---------------------------------------------------
__device__ __forceinline__ void atomicMaxF(float* addr, float v) {
    if (v >= 0.0f) atomicMax((int*)addr, __float_as_int(v));
    else           atomicMin((unsigned int*)addr, (unsigned int)__float_as_int(v));
}

__device__ __forceinline__ void load_edge(const void* ei, int e, int E, int& src, int& dst) {
    if (g_is64) {
        const long long* p = (const long long*)ei;
        src = (int)p[e]; dst = (int)p[E + e];
    } else {
        const int* p = (const int*)ei;
        src = p[e]; dst = p[E + e];
    }
}

// ---------------- dtype detection: odd 32-bit words all zero => int64 -------
__global__ void detect_kernel(const unsigned int* __restrict__ w, int nwords)
{
    int i = blockIdx.x * blockDim.x + threadIdx.x;
    int odd = 2 * i + 1;
    if (odd < nwords && w[odd] != 0u) g_is64 = 0;
}

// ---------------- tiled fp32 GEMM: C = A[M,K] @ B[K,N] (+bias) (+relu) ------
// BM=128, BN=64, BK=16, 256 threads, 8x4 per thread, LDS.128 inner reads.
__global__ void sgemm_kernel(const float* __restrict__ Aext, int a_id,
                             const float* __restrict__ B,
                             const float* __restrict__ bias,
                             float* __restrict__ Cext, int c_id,
                             int M, int N, int K, int relu)
{
    const float* A = (a_id > 0) ? buf_sel(a_id) : Aext;
    float*       C = (c_id > 0) ? buf_sel(c_id) : Cext;

    const int BM = 128, BN = 64, BK = 16;
    __shared__ __align__(16) float As[BK][BM];
    __shared__ __align__(16) float Bs[BK][BN];

    int tid = threadIdx.x;
    int bm = blockIdx.y * BM;
    int bn = blockIdx.x * BN;

    int arow = tid >> 2;          // 0..63
    int acol = (tid & 3) * 4;     // 0,4,8,12
    int brow = tid >> 4;          // 0..15
    int bcol = (tid & 15) * 4;    // 0..60

    int ty = tid >> 4;            // 0..15 -> 8 rows each
    int tx = tid & 15;            // 0..15 -> 4 cols each

    float acc[8][4];
    #pragma unroll
    for (int i = 0; i < 8; i++)
        #pragma unroll
        for (int j = 0; j < 4; j++) acc[i][j] = 0.0f;

    for (int k0 = 0; k0 < K; k0 += BK) {
        #pragma unroll
        for (int r = 0; r < 2; r++) {
            int m = bm + arow + r * 64;
            float4 v = (m < M) ? *(const float4*)(A + (size_t)m * K + k0 + acol)
                               : make_float4(0.f, 0.f, 0.f, 0.f);
            As[acol + 0][arow + r * 64] = v.x;
            As[acol + 1][arow + r * 64] = v.y;
            As[acol + 2][arow + r * 64] = v.z;
            As[acol + 3][arow + r * 64] = v.w;
        }
        float4 vb = *(const float4*)(B + (size_t)(k0 + brow) * N + bn + bcol);
        *(float4*)&Bs[brow][bcol] = vb;
        __syncthreads();

        #pragma unroll
        for (int kk = 0; kk < BK; kk++) {
            float4 a0 = *(const float4*)&As[kk][ty * 8];
            float4 a1 = *(const float4*)&As[kk][ty * 8 + 4];
            float4 b  = *(const float4*)&Bs[kk][tx * 4];
            float a[8] = {a0.x, a0.y, a0.z, a0.w, a1.x, a1.y, a1.z, a1.w};
            float bb[4] = {b.x, b.y, b.z, b.w};
            #pragma unroll
            for (int i = 0; i < 8; i++)
                #pragma unroll
                for (int j = 0; j < 4; j++) acc[i][j] = fmaf(a[i], bb[j], acc[i][j]);
        }
        __syncthreads();
    }

    #pragma unroll
    for (int i = 0; i < 8; i++) {
        int m = bm + ty * 8 + i;
        if (m >= M) continue;
        #pragma unroll
        for (int j = 0; j < 4; j++) {
            int n = bn + tx * 4 + j;
            float v = acc[i][j];
            if (bias) v += bias[n];
            if (relu) v = fmaxf(v, 0.0f);
            C[(size_t)m * N + n] = v;
        }
    }
}

// ---------------- attention scores: a_src/a_dst per (node, head) ------------
__global__ void att_kernel(const float* __restrict__ att_src, const float* __restrict__ att_dst)
{
    int i = blockIdx.x * blockDim.x + threadIdx.x;
    if (i >= NN * HEADS) return;
    int n = i >> 1, h = i & 1;
    const float4* row = (const float4*)(g_xp + (size_t)n * FEAT + h * OUTC);
    const float4* ws  = (const float4*)(att_src + h * OUTC);
    const float4* wd  = (const float4*)(att_dst + h * OUTC);
    float s = 0.f, d = 0.f;
    #pragma unroll
    for (int c = 0; c < OUTC / 4; c++) {
        float4 x = row[c], a = ws[c], b = wd[c];
        s += x.x * a.x + x.y * a.y + x.z * a.z + x.w * a.w;
        d += x.x * b.x + x.y * b.y + x.z * b.z + x.w * b.w;
    }
    g_asrc[i] = s;
    g_adst[i] = d;
}

// ---------------- init: amax=-inf-ish, denom=0, accum=0 ---------------------
__global__ void init_kernel()
{
    int i = blockIdx.x * blockDim.x + threadIdx.x;
    if (i < NN * FEAT) g_accum[i] = 0.0f;
    if (i < NN * HEADS) { g_amax[i] = -1e30f; g_denom[i] = 0.0f; }
}

// ---------------- pass A: segment max of leaky_relu(a_src+a_dst) over dst ---
__global__ void pass_a_kernel(const void* __restrict__ ei, int E, int ET)
{
    int e = blockIdx.x * blockDim.x + threadIdx.x;
    if (e >= ET) return;
    int src, dst;
    if (e < E) load_edge(ei, e, E, src, dst);
    else       src = dst = e - E;
    if ((unsigned)src >= NN || (unsigned)dst >= NN) return;  // safety net
    #pragma unroll
    for (int h = 0; h < HEADS; h++) {
        float a = g_asrc[src * HEADS + h] + g_adst[dst * HEADS + h];
        a = a > 0.f ? a : NEG_SLOPE * a;
        atomicMaxF(&g_amax[dst * HEADS + h], a);
    }
}

// ---------------- pass B: one warp per edge; accumulate p and p*xp[src] -----
__global__ void pass_b_kernel(const void* __restrict__ ei, int E, int ET)
{
    int gt = blockIdx.x * blockDim.x + threadIdx.x;
    int e = gt >> 5;
    int lane = gt & 31;
    if (e >= ET) return;
    int src, dst;
    if (e < E) load_edge(ei, e, E, src, dst);
    else       src = dst = e - E;
    if ((unsigned)src >= NN || (unsigned)dst >= NN) return;  // safety net

    float a0 = g_asrc[src * 2 + 0] + g_adst[dst * 2 + 0];
    float a1 = g_asrc[src * 2 + 1] + g_adst[dst * 2 + 1];
    a0 = a0 > 0.f ? a0 : NEG_SLOPE * a0;
    a1 = a1 > 0.f ? a1 : NEG_SLOPE * a1;
    float p0 = expf(a0 - g_amax[dst * 2 + 0]);
    float p1 = expf(a1 - g_amax[dst * 2 + 1]);

    if (lane == 0) atomicAdd(&g_denom[dst * 2 + 0], p0);
    if (lane == 1) atomicAdd(&g_denom[dst * 2 + 1], p1);

    const float4* xs = (const float4*)(g_xp + (size_t)src * FEAT);
    float4*       ac = (float4*)(g_accum + (size_t)dst * FEAT);

    // 64 float4 per edge: lane handles index lane (head 0) and lane+32 (head 1)
    float4 v0 = xs[lane];
    atomicAdd(&ac[lane],      make_float4(v0.x * p0, v0.y * p0, v0.z * p0, v0.w * p0));
    float4 v1 = xs[lane + 32];
    atomicAdd(&ac[lane + 32], make_float4(v1.x * p1, v1.y * p1, v1.z * p1, v1.w * p1));
}

// ---------------- finalize: accum = accum/denom + bias_g (in place) ---------
__global__ void finalize_kernel(const float* __restrict__ bias_g)
{
    int i = blockIdx.x * blockDim.x + threadIdx.x;
    if (i >= NN * FEAT) return;
    int n = i >> 8;          // /256
    int j = i & 255;
    int h = j >> 7;          // /128
    float d = fmaxf(g_denom[n * HEADS + h], 1e-16f);
    g_accum[i] = g_accum[i] / d + bias_g[j];
}

// ---------------- launch ----------------------------------------------------
extern "C" void kernel_launch(void* const* d_in, const int* in_sizes, int n_in,
                              void* d_out, int out_size)
{
    const float* z       = (const float*)d_in[0];
    const void*  ei      = d_in[1];
    const float* W1      = (const float*)d_in[2];
    const float* b1      = (const float*)d_in[3];
    const float* W2      = (const float*)d_in[4];
    const float* b2      = (const float*)d_in[5];
    const float* Wg      = (const float*)d_in[6];
    const float* att_src = (const float*)d_in[7];
    const float* att_dst = (const float*)d_in[8];
    const float* bias_g  = (const float*)d_in[9];
    const float* W3      = (const float*)d_in[10];
    const float* b3      = (const float*)d_in[11];
    float*       out     = (float*)d_out;

    int E  = in_sizes[1] / 2;   // element count / 2 (same for int32 or int64)
    int ET = E + NN;

    // 0) sniff edge_index dtype (first 4096 32-bit words; safe for both dtypes)
    {
        int nwords = 4096;
        if (nwords > in_sizes[1]) nwords = in_sizes[1];
        detect_kernel<<<(nwords / 2 + 255) / 256, 256>>>((const unsigned int*)ei, nwords);
    }
    // 1) x1 = relu(z @ W1 + b1): [20000,512]x[512,256] -> g_x1
    {
        dim3 grid(HID / 64, (NN + 127) / 128);
        sgemm_kernel<<<grid, 256>>>(z, 0, W1, b1, nullptr, 1, NN, HID, LATENT, 1);
    }
    // 2) x2 = relu(x1 @ W2 + b2): [20000,256]x[256,512] -> g_x2
    {
        dim3 grid((HID * HEADS) / 64, (NN + 127) / 128);
        sgemm_kernel<<<grid, 256>>>(nullptr, 1, W2, b2, nullptr, 2, NN, HID * HEADS, HID, 1);
    }
    // 3) xp = x2 @ Wg: [20000,512]x[512,256] -> g_xp
    {
        dim3 grid(FEAT / 64, (NN + 127) / 128);
        sgemm_kernel<<<grid, 256>>>(nullptr, 2, Wg, nullptr, nullptr, 3, NN, FEAT, HID * HEADS, 0);
    }
    // 4) attention scores
    att_kernel<<<(NN * HEADS + 255) / 256, 256>>>(att_src, att_dst);
    // 5) init accum/amax/denom
    init_kernel<<<(NN * FEAT + 255) / 256, 256>>>();
    // 6) segment max
    pass_a_kernel<<<(ET + 255) / 256, 256>>>(ei, E, ET);
    // 7) accumulate messages (warp per edge)
    {
        long long total = (long long)ET * 32;
        pass_b_kernel<<<(int)((total + 255) / 256), 256>>>(ei, E, ET);
    }
    // 8) normalize + bias_g
    finalize_kernel<<<(NN * FEAT + 255) / 256, 256>>>(bias_g);
    // 9) out = xgat @ W3 + b3: [20000,256]x[256,512] -> d_out
    {
        dim3 grid(512 / 64, (NN + 127) / 128);
        sgemm_kernel<<<grid, 256>>>(nullptr, 4, W3, b3, out, 0, NN, 512, FEAT, 0);
    }
}

// round 7
// speedup vs baseline: 1.4370x; 1.4370x over previous
#include <cuda_runtime.h>
#include <cuda_bf16.h>
#include <math.h>
#include <stdint.h>

// Problem constants (fixed shapes)
#define NN      20000
#define LATENT  512
#define HID     256
#define OUTC    128
#define HEADS   2
#define FEAT    (HEADS*OUTC)   // 256
#define NEG_SLOPE 0.2f

// ---------------- scratch (static device globals; 16B aligned for float4) ---
__device__ __align__(16) float g_x1[NN * HID];          // relu(z@W1+b1)   [20000,256]
__device__ __align__(16) float g_x2[NN * (HID*HEADS)];  // relu(x1@W2+b2)  [20000,512]
__device__ __align__(16) float g_xp[NN * FEAT];         // x2@Wg           [20000,256]
__device__ __align__(16) float g_asrc[NN * HEADS];
__device__ __align__(16) float g_adst[NN * HEADS];
__device__ __align__(16) float g_amax[NN * HEADS];
__device__ __align__(16) float g_denom[NN * HEADS];
__device__ __align__(16) float g_accum[NN * FEAT];      // unnormalized msg sum

// edge_index dtype flag: 1 = int64, 0 = int32. Monotonic -> deterministic.
__device__ int g_is64 = 1;

__device__ __forceinline__ float* buf_sel(int id) {
    switch (id) {
        case 1: return g_x1;
        case 2: return g_x2;
        case 3: return g_xp;
        case 4: return g_accum;
    }
    return nullptr;
}

// ---------------- helpers ---------------------------------------------------
__device__ __forceinline__ void atomicMaxF(float* addr, float v) {
    if (v >= 0.0f) atomicMax((int*)addr, __float_as_int(v));
    else           atomicMin((unsigned int*)addr, (unsigned int)__float_as_int(v));
}

__device__ __forceinline__ void load_edge(const void* ei, int e, int E, int& src, int& dst) {
    if (g_is64) {
        const long long* p = (const long long*)ei;
        src = (int)p[e]; dst = (int)p[E + e];
    } else {
        const int* p = (const int*)ei;
        src = p[e]; dst = p[E + e];
    }
}

__device__ __forceinline__ uint32_t f2tf32(float f) {
    uint32_t r;
    asm("cvt.rna.tf32.f32 %0, %1;" : "=r"(r) : "f"(f));
    return r;
}

__device__ __forceinline__ void mma_tf32(float c[4],
                                         const uint32_t a[4],
                                         uint32_t b0, uint32_t b1)
{
    asm volatile(
        "mma.sync.aligned.m16n8k8.row.col.f32.tf32.tf32.f32 "
        "{%0,%1,%2,%3}, {%4,%5,%6,%7}, {%8,%9}, {%0,%1,%2,%3};"
        : "+f"(c[0]), "+f"(c[1]), "+f"(c[2]), "+f"(c[3])
        : "r"(a[0]), "r"(a[1]), "r"(a[2]), "r"(a[3]), "r"(b0), "r"(b1));
}

// ---------------- dtype detection: odd 32-bit words all zero => int64 -------
__global__ void detect_kernel(const unsigned int* __restrict__ w, int nwords)
{
    int i = blockIdx.x * blockDim.x + threadIdx.x;
    int odd = 2 * i + 1;
    if (odd < nwords && w[odd] != 0u) g_is64 = 0;
}

// ---------------- tf32 tensor-core GEMM: C = A[M,K] @ B[K,N] (+bias)(+relu) -
// BM=128, BN=128, BK=32. 256 threads = 8 warps (4 m x 2 n), warp tile 32x64.
// mma.sync m16n8k8 tf32, fp32 accumulate.
__global__ void __launch_bounds__(256, 2)
tf32_gemm_kernel(const float* __restrict__ Aext, int a_id,
                 const float* __restrict__ B,
                 const float* __restrict__ bias,
                 float* __restrict__ Cext, int c_id,
                 int M, int N, int K, int relu)
{
    const float* A = (a_id > 0) ? buf_sel(a_id) : Aext;
    float*       C = (c_id > 0) ? buf_sel(c_id) : Cext;

    __shared__ uint32_t As[128][36];   // [m][k] tf32 bits, pad->conflict-free frag loads
    __shared__ uint32_t Bs[32][132];   // [k][n] tf32 bits

    const int tid  = threadIdx.x;
    const int warp = tid >> 5;
    const int lane = tid & 31;
    const int gid  = lane >> 2;   // 0..7
    const int tig  = lane & 3;    // 0..3

    const int bm = blockIdx.y * 128;
    const int bn = blockIdx.x * 128;
    const int warp_m = warp >> 1;   // 0..3  -> 32 rows
    const int warp_n = warp & 1;    // 0..1  -> 64 cols

    float c[2][8][4];
    #pragma unroll
    for (int mt = 0; mt < 2; mt++)
        #pragma unroll
        for (int nt = 0; nt < 8; nt++)
            #pragma unroll
            for (int i = 0; i < 4; i++) c[mt][nt][i] = 0.0f;

    // global->smem mapping (64B contiguous per thread, fully coalesced)
    const int a_row = tid >> 1;             // 0..127
    const int a_col = (tid & 1) * 16;       // float col base (4 float4)
    const int b_row = tid >> 3;             // 0..31
    const int b_col = (tid & 7) * 16;       // float col base

    for (int k0 = 0; k0 < K; k0 += 32) {
        // A tile: 128 x 32
        {
            int m = bm + a_row;
            const float* src = A + (size_t)m * K + k0 + a_col;
            #pragma unroll
            for (int i = 0; i < 4; i++) {
                float4 v = (m < M) ? *(const float4*)(src + i * 4)
                                   : make_float4(0.f, 0.f, 0.f, 0.f);
                uint32_t* d = &As[a_row][a_col + i * 4];
                d[0] = f2tf32(v.x); d[1] = f2tf32(v.y);
                d[2] = f2tf32(v.z); d[3] = f2tf32(v.w);
            }
        }
        // B tile: 32 x 128
        {
            const float* src = B + (size_t)(k0 + b_row) * N + bn + b_col;
            #pragma unroll
            for (int i = 0; i < 4; i++) {
                float4 v = *(const float4*)(src + i * 4);
                uint32_t* d = &Bs[b_row][b_col + i * 4];
                d[0] = f2tf32(v.x); d[1] = f2tf32(v.y);
                d[2] = f2tf32(v.z); d[3] = f2tf32(v.w);
            }
        }
        __syncthreads();

        #pragma unroll
        for (int kk = 0; kk < 4; kk++) {
            const int k = kk * 8;
            uint32_t a[2][4];
            #pragma unroll
            for (int mt = 0; mt < 2; mt++) {
                int r = warp_m * 32 + mt * 16;
                a[mt][0] = As[r + gid    ][k + tig    ];
                a[mt][1] = As[r + gid + 8][k + tig    ];
                a[mt][2] = As[r + gid    ][k + tig + 4];
                a[mt][3] = As[r + gid + 8][k + tig + 4];
            }
            #pragma unroll
            for (int nt = 0; nt < 8; nt++) {
                int n = warp_n * 64 + nt * 8;
                uint32_t b0 = Bs[k + tig    ][n + gid];
                uint32_t b1 = Bs[k + tig + 4][n + gid];
                mma_tf32(c[0][nt], a[0], b0, b1);
                mma_tf32(c[1][nt], a[1], b0, b1);
            }
        }
        __syncthreads();
    }

    // epilogue
    #pragma unroll
    for (int nt = 0; nt < 8; nt++) {
        int col = bn + warp_n * 64 + nt * 8 + 2 * tig;
        float bb0 = bias ? bias[col]     : 0.0f;
        float bb1 = bias ? bias[col + 1] : 0.0f;
        #pragma unroll
        for (int mt = 0; mt < 2; mt++) {
            int row0 = bm + warp_m * 32 + mt * 16 + gid;
            float v0 = c[mt][nt][0] + bb0;
            float v1 = c[mt][nt][1] + bb1;
            float v2 = c[mt][nt][2] + bb0;
            float v3 = c[mt][nt][3] + bb1;
            if (relu) {
                v0 = fmaxf(v0, 0.f); v1 = fmaxf(v1, 0.f);
                v2 = fmaxf(v2, 0.f); v3 = fmaxf(v3, 0.f);
            }
            if (row0 < M)     *(float2*)(C + (size_t)row0 * N + col)       = make_float2(v0, v1);
            if (row0 + 8 < M) *(float2*)(C + (size_t)(row0 + 8) * N + col) = make_float2(v2, v3);
        }
    }
}

// ---------------- attention scores: a_src/a_dst per (node, head) ------------
__global__ void att_kernel(const float* __restrict__ att_src, const float* __restrict__ att_dst)
{
    int i = blockIdx.x * blockDim.x + threadIdx.x;
    if (i >= NN * HEADS) return;
    int n = i >> 1, h = i & 1;
    const float4* row = (const float4*)(g_xp + (size_t)n * FEAT + h * OUTC);
    const float4* ws  = (const float4*)(att_src + h * OUTC);
    const float4* wd  = (const float4*)(att_dst + h * OUTC);
    float s = 0.f, d = 0.f;
    #pragma unroll
    for (int c = 0; c < OUTC / 4; c++) {
        float4 x = row[c], a = ws[c], b = wd[c];
        s += x.x * a.x + x.y * a.y + x.z * a.z + x.w * a.w;
        d += x.x * b.x + x.y * b.y + x.z * b.z + x.w * b.w;
    }
    g_asrc[i] = s;
    g_adst[i] = d;
}

// ---------------- init: amax=-inf-ish, denom=0, accum=0 ---------------------
__global__ void init_kernel()
{
    int i = blockIdx.x * blockDim.x + threadIdx.x;
    if (i < NN * FEAT) g_accum[i] = 0.0f;
    if (i < NN * HEADS) { g_amax[i] = -1e30f; g_denom[i] = 0.0f; }
}

// ---------------- pass A: segment max of leaky_relu(a_src+a_dst) over dst ---
__global__ void pass_a_kernel(const void* __restrict__ ei, int E, int ET)
{
    int e = blockIdx.x * blockDim.x + threadIdx.x;
    if (e >= ET) return;
    int src, dst;
    if (e < E) load_edge(ei, e, E, src, dst);
    else       src = dst = e - E;
    if ((unsigned)src >= NN || (unsigned)dst >= NN) return;  // safety net
    #pragma unroll
    for (int h = 0; h < HEADS; h++) {
        float a = g_asrc[src * HEADS + h] + g_adst[dst * HEADS + h];
        a = a > 0.f ? a : NEG_SLOPE * a;
        atomicMaxF(&g_amax[dst * HEADS + h], a);
    }
}

// ---------------- pass B: one warp per edge; accumulate p and p*xp[src] -----
__global__ void pass_b_kernel(const void* __restrict__ ei, int E, int ET)
{
    int gt = blockIdx.x * blockDim.x + threadIdx.x;
    int e = gt >> 5;
    int lane = gt & 31;
    if (e >= ET) return;
    int src, dst;
    if (e < E) load_edge(ei, e, E, src, dst);
    else       src = dst = e - E;
    if ((unsigned)src >= NN || (unsigned)dst >= NN) return;  // safety net

    float a0 = g_asrc[src * 2 + 0] + g_adst[dst * 2 + 0];
    float a1 = g_asrc[src * 2 + 1] + g_adst[dst * 2 + 1];
    a0 = a0 > 0.f ? a0 : NEG_SLOPE * a0;
    a1 = a1 > 0.f ? a1 : NEG_SLOPE * a1;
    float p0 = expf(a0 - g_amax[dst * 2 + 0]);
    float p1 = expf(a1 - g_amax[dst * 2 + 1]);

    if (lane == 0) atomicAdd(&g_denom[dst * 2 + 0], p0);
    if (lane == 1) atomicAdd(&g_denom[dst * 2 + 1], p1);

    const float4* xs = (const float4*)(g_xp + (size_t)src * FEAT);
    float4*       ac = (float4*)(g_accum + (size_t)dst * FEAT);

    float4 v0 = xs[lane];
    atomicAdd(&ac[lane],      make_float4(v0.x * p0, v0.y * p0, v0.z * p0, v0.w * p0));
    float4 v1 = xs[lane + 32];
    atomicAdd(&ac[lane + 32], make_float4(v1.x * p1, v1.y * p1, v1.z * p1, v1.w * p1));
}

// ---------------- finalize: accum = accum/denom + bias_g (in place) ---------
__global__ void finalize_kernel(const float* __restrict__ bias_g)
{
    int i = blockIdx.x * blockDim.x + threadIdx.x;
    if (i >= NN * FEAT) return;
    int n = i >> 8;          // /256
    int j = i & 255;
    int h = j >> 7;          // /128
    float d = fmaxf(g_denom[n * HEADS + h], 1e-16f);
    g_accum[i] = g_accum[i] / d + bias_g[j];
}

// ---------------- launch ----------------------------------------------------
extern "C" void kernel_launch(void* const* d_in, const int* in_sizes, int n_in,
                              void* d_out, int out_size)
{
    const float* z       = (const float*)d_in[0];
    const void*  ei      = d_in[1];
    const float* W1      = (const float*)d_in[2];
    const float* b1      = (const float*)d_in[3];
    const float* W2      = (const float*)d_in[4];
    const float* b2      = (const float*)d_in[5];
    const float* Wg      = (const float*)d_in[6];
    const float* att_src = (const float*)d_in[7];
    const float* att_dst = (const float*)d_in[8];
    const float* bias_g  = (const float*)d_in[9];
    const float* W3      = (const float*)d_in[10];
    const float* b3      = (const float*)d_in[11];
    float*       out     = (float*)d_out;

    int E  = in_sizes[1] / 2;
    int ET = E + NN;

    // 0) sniff edge_index dtype
    {
        int nwords = 4096;
        if (nwords > in_sizes[1]) nwords = in_sizes[1];
        detect_kernel<<<(nwords / 2 + 255) / 256, 256>>>((const unsigned int*)ei, nwords);
    }
    // 1) x1 = relu(z @ W1 + b1): [20000,512]x[512,256] -> g_x1
    {
        dim3 grid(HID / 128, (NN + 127) / 128);
        tf32_gemm_kernel<<<grid, 256>>>(z, 0, W1, b1, nullptr, 1, NN, HID, LATENT, 1);
    }
    // 2) x2 = relu(x1 @ W2 + b2): [20000,256]x[256,512] -> g_x2
    {
        dim3 grid((HID * HEADS) / 128, (NN + 127) / 128);
        tf32_gemm_kernel<<<grid, 256>>>(nullptr, 1, W2, b2, nullptr, 2, NN, HID * HEADS, HID, 1);
    }
    // 3) xp = x2 @ Wg: [20000,512]x[512,256] -> g_xp
    {
        dim3 grid(FEAT / 128, (NN + 127) / 128);
        tf32_gemm_kernel<<<grid, 256>>>(nullptr, 2, Wg, nullptr, nullptr, 3, NN, FEAT, HID * HEADS, 0);
    }
    // 4) attention scores
    att_kernel<<<(NN * HEADS + 255) / 256, 256>>>(att_src, att_dst);
    // 5) init accum/amax/denom
    init_kernel<<<(NN * FEAT + 255) / 256, 256>>>();
    // 6) segment max
    pass_a_kernel<<<(ET + 255) / 256, 256>>>(ei, E, ET);
    // 7) accumulate messages (warp per edge)
    {
        long long total = (long long)ET * 32;
        pass_b_kernel<<<(int)((total + 255) / 256), 256>>>(ei, E, ET);
    }
    // 8) normalize + bias_g
    finalize_kernel<<<(NN * FEAT + 255) / 256, 256>>>(bias_g);
    // 9) out = xgat @ W3 + b3: [20000,256]x[256,512] -> d_out
    {
        dim3 grid(512 / 128, (NN + 127) / 128);
        tf32_gemm_kernel<<<grid, 256>>>(nullptr, 4, W3, b3, out, 0, NN, 512, FEAT, 0);
    }
}

// round 9
// speedup vs baseline: 1.7022x; 1.1845x over previous
#include <cuda_runtime.h>
#include <cuda_bf16.h>
#include <math.h>
#include <stdint.h>

// Problem constants (fixed shapes)
#define NN      20000
#define LATENT  512
#define HID     256
#define OUTC    128
#define HEADS   2
#define FEAT    (HEADS*OUTC)   // 256
#define NEG_SLOPE 0.2f

// ---------------- scratch (static device globals; 16B aligned for float4) ---
__device__ __align__(16) float g_x1[NN * HID];          // relu(z@W1+b1)   [20000,256]
__device__ __align__(16) float g_x2[NN * (HID*HEADS)];  // relu(x1@W2+b2)  [20000,512]
__device__ __align__(16) float g_xp[NN * FEAT];         // x2@Wg           [20000,256]
__device__ __align__(16) float g_asrc[NN * HEADS];
__device__ __align__(16) float g_adst[NN * HEADS];
__device__ __align__(16) float g_amax[NN * HEADS];
__device__ __align__(16) float g_denom[NN * HEADS];
__device__ __align__(16) float g_accum[NN * FEAT];      // unnormalized msg sum

// edge_index dtype flag: 1 = int64, 0 = int32. Monotonic -> deterministic.
__device__ int g_is64 = 1;

__device__ __forceinline__ float* buf_sel(int id) {
    switch (id) {
        case 1: return g_x1;
        case 2: return g_x2;
        case 3: return g_xp;
        case 4: return g_accum;
    }
    return nullptr;
}

// ---------------- helpers ---------------------------------------------------
__device__ __forceinline__ void atomicMaxF(float* addr, float v) {
    if (v >= 0.0f) atomicMax((int*)addr, __float_as_int(v));
    else           atomicMin((unsigned int*)addr, (unsigned int)__float_as_int(v));
}

__device__ __forceinline__ void load_edge(const void* ei, int e, int E, int& src, int& dst) {
    if (g_is64) {
        const long long* p = (const long long*)ei;
        src = (int)p[e]; dst = (int)p[E + e];
    } else {
        const int* p = (const int*)ei;
        src = p[e]; dst = p[E + e];
    }
}

__device__ __forceinline__ uint32_t f2tf32(float f) {
    uint32_t r;
    asm("cvt.rna.tf32.f32 %0, %1;" : "=r"(r) : "f"(f));
    return r;
}

__device__ __forceinline__ uint4 cvt4(float4 v) {
    uint4 r;
    r.x = f2tf32(v.x); r.y = f2tf32(v.y); r.z = f2tf32(v.z); r.w = f2tf32(v.w);
    return r;
}

__device__ __forceinline__ void mma_tf32(float c[4],
                                         const uint32_t a[4],
                                         uint32_t b0, uint32_t b1)
{
    asm volatile(
        "mma.sync.aligned.m16n8k8.row.col.f32.tf32.tf32.f32 "
        "{%0,%1,%2,%3}, {%4,%5,%6,%7}, {%8,%9}, {%0,%1,%2,%3};"
        : "+f"(c[0]), "+f"(c[1]), "+f"(c[2]), "+f"(c[3])
        : "r"(a[0]), "r"(a[1]), "r"(a[2]), "r"(a[3]), "r"(b0), "r"(b1));
}

// ---------------- dtype detection: odd 32-bit words all zero => int64 -------
__global__ void detect_kernel(const unsigned int* __restrict__ w, int nwords)
{
    int i = blockIdx.x * blockDim.x + threadIdx.x;
    int odd = 2 * i + 1;
    if (odd < nwords && w[odd] != 0u) g_is64 = 0;
}

// ---------------- tf32 tensor-core GEMM, software-pipelined -----------------
// BM=128, BN=128, BK=16. 256 threads = 8 warps (4m x 2n), warp tile 32x64.
// Double-buffered smem, register prefetch of the next tile, one sync/tile.
// As row stride 20 -> frag-read banks 20*gid+tig : all distinct (conflict-free)
// Bs row stride 136 -> frag-read banks 8*tig+gid : all distinct (conflict-free)
#define AS_STRIDE 20
#define BS_STRIDE 136

__global__ void __launch_bounds__(256, 2)
tf32_gemm_kernel(const float* __restrict__ Aext, int a_id,
                 const float* __restrict__ B,
                 const float* __restrict__ bias,
                 float* __restrict__ Cext, int c_id,
                 int M, int N, int K, int relu)
{
    const float* A = (a_id > 0) ? buf_sel(a_id) : Aext;
    float*       C = (c_id > 0) ? buf_sel(c_id) : Cext;

    __shared__ uint32_t As[2][128][AS_STRIDE];
    __shared__ uint32_t Bs[2][16][BS_STRIDE];

    const int tid  = threadIdx.x;
    const int warp = tid >> 5;
    const int lane = tid & 31;
    const int gid  = lane >> 2;   // 0..7
    const int tig  = lane & 3;    // 0..3

    const int bm = blockIdx.y * 128;
    const int bn = blockIdx.x * 128;
    const int warp_m = warp >> 1;   // 0..3
    const int warp_n = warp & 1;    // 0..1

    float c[2][8][4];
    #pragma unroll
    for (int mt = 0; mt < 2; mt++)
        #pragma unroll
        for (int nt = 0; nt < 8; nt++)
            #pragma unroll
            for (int i = 0; i < 4; i++) c[mt][nt][i] = 0.0f;

    // staging mapping: A row-per-2-threads (8 floats each), B row-per-16-threads
    const int a_row = tid >> 1;            // 0..127
    const int a_col = (tid & 1) * 8;       // 0 or 8
    const int b_row = tid >> 4;            // 0..15
    const int b_col = (tid & 15) * 8;      // 0..120

    const bool a_ok = (bm + a_row) < M;
    const float* aptr = A + (size_t)(bm + a_row) * K + a_col;
    const float* bptr = B + (size_t)b_row * N + bn + b_col;

    const float4 fz = make_float4(0.f, 0.f, 0.f, 0.f);
    float4 ra0, ra1, rb0, rb1;

    // ---- prologue: load tile 0, stage to buffer 0
    ra0 = a_ok ? *(const float4*)(aptr)     : fz;
    ra1 = a_ok ? *(const float4*)(aptr + 4) : fz;
    rb0 = *(const float4*)(bptr);
    rb1 = *(const float4*)(bptr + 4);
    *(uint4*)&As[0][a_row][a_col]     = cvt4(ra0);
    *(uint4*)&As[0][a_row][a_col + 4] = cvt4(ra1);
    *(uint4*)&Bs[0][b_row][b_col]     = cvt4(rb0);
    *(uint4*)&Bs[0][b_row][b_col + 4] = cvt4(rb1);
    __syncthreads();

    const int T = K >> 4;   // tiles of BK=16
    for (int t = 0; t < T; t++) {
        const int cur = t & 1;
        // prefetch next tile into registers (latency hidden behind mma)
        if (t + 1 < T) {
            const float* ap = aptr + (t + 1) * 16;
            const float* bp = bptr + (size_t)(t + 1) * 16 * N;
            ra0 = a_ok ? *(const float4*)(ap)     : fz;
            ra1 = a_ok ? *(const float4*)(ap + 4) : fz;
            rb0 = *(const float4*)(bp);
            rb1 = *(const float4*)(bp + 4);
        }

        // compute on buffer `cur`
        #pragma unroll
        for (int kk = 0; kk < 2; kk++) {
            const int k = kk * 8;
            uint32_t a[2][4];
            #pragma unroll
            for (int mt = 0; mt < 2; mt++) {
                int r = warp_m * 32 + mt * 16;
                a[mt][0] = As[cur][r + gid    ][k + tig    ];
                a[mt][1] = As[cur][r + gid + 8][k + tig    ];
                a[mt][2] = As[cur][r + gid    ][k + tig + 4];
                a[mt][3] = As[cur][r + gid + 8][k + tig + 4];
            }
            #pragma unroll
            for (int nt = 0; nt < 8; nt++) {
                int n = warp_n * 64 + nt * 8;
                uint32_t b0 = Bs[cur][k + tig    ][n + gid];
                uint32_t b1 = Bs[cur][k + tig + 4][n + gid];
                mma_tf32(c[0][nt], a[0], b0, b1);
                mma_tf32(c[1][nt], a[1], b0, b1);
            }
        }

        // stage next tile into the other buffer
        if (t + 1 < T) {
            const int nxt = cur ^ 1;
            *(uint4*)&As[nxt][a_row][a_col]     = cvt4(ra0);
            *(uint4*)&As[nxt][a_row][a_col + 4] = cvt4(ra1);
            *(uint4*)&Bs[nxt][b_row][b_col]     = cvt4(rb0);
            *(uint4*)&Bs[nxt][b_row][b_col + 4] = cvt4(rb1);
        }
        __syncthreads();
    }

    // ---- epilogue
    #pragma unroll
    for (int nt = 0; nt < 8; nt++) {
        int col = bn + warp_n * 64 + nt * 8 + 2 * tig;
        float bb0 = bias ? bias[col]     : 0.0f;
        float bb1 = bias ? bias[col + 1] : 0.0f;
        #pragma unroll
        for (int mt = 0; mt < 2; mt++) {
            int row0 = bm + warp_m * 32 + mt * 16 + gid;
            float v0 = c[mt][nt][0] + bb0;
            float v1 = c[mt][nt][1] + bb1;
            float v2 = c[mt][nt][2] + bb0;
            float v3 = c[mt][nt][3] + bb1;
            if (relu) {
                v0 = fmaxf(v0, 0.f); v1 = fmaxf(v1, 0.f);
                v2 = fmaxf(v2, 0.f); v3 = fmaxf(v3, 0.f);
            }
            if (row0 < M)     *(float2*)(C + (size_t)row0 * N + col)       = make_float2(v0, v1);
            if (row0 + 8 < M) *(float2*)(C + (size_t)(row0 + 8) * N + col) = make_float2(v2, v3);
        }
    }
}

// ---------------- attention scores: a_src/a_dst per (node, head) ------------
__global__ void att_kernel(const float* __restrict__ att_src, const float* __restrict__ att_dst)
{
    int i = blockIdx.x * blockDim.x + threadIdx.x;
    if (i >= NN * HEADS) return;
    int n = i >> 1, h = i & 1;
    const float4* row = (const float4*)(g_xp + (size_t)n * FEAT + h * OUTC);
    const float4* ws  = (const float4*)(att_src + h * OUTC);
    const float4* wd  = (const float4*)(att_dst + h * OUTC);
    float s = 0.f, d = 0.f;
    #pragma unroll
    for (int c = 0; c < OUTC / 4; c++) {
        float4 x = row[c], a = ws[c], b = wd[c];
        s += x.x * a.x + x.y * a.y + x.z * a.z + x.w * a.w;
        d += x.x * b.x + x.y * b.y + x.z * b.z + x.w * b.w;
    }
    g_asrc[i] = s;
    g_adst[i] = d;
}

// ---------------- init: amax=-inf-ish, denom=0, accum=0 ---------------------
__global__ void init_kernel()
{
    int i = blockIdx.x * blockDim.x + threadIdx.x;
    if (i < NN * FEAT) g_accum[i] = 0.0f;
    if (i < NN * HEADS) { g_amax[i] = -1e30f; g_denom[i] = 0.0f; }
}

// ---------------- pass A: segment max of leaky_relu(a_src+a_dst) over dst ---
__global__ void pass_a_kernel(const void* __restrict__ ei, int E, int ET)
{
    int e = blockIdx.x * blockDim.x + threadIdx.x;
    if (e >= ET) return;
    int src, dst;
    if (e < E) load_edge(ei, e, E, src, dst);
    else       src = dst = e - E;
    if ((unsigned)src >= NN || (unsigned)dst >= NN) return;  // safety net
    #pragma unroll
    for (int h = 0; h < HEADS; h++) {
        float a = g_asrc[src * HEADS + h] + g_adst[dst * HEADS + h];
        a = a > 0.f ? a : NEG_SLOPE * a;
        atomicMaxF(&g_amax[dst * HEADS + h], a);
    }
}

// ---------------- pass B: one warp per edge; accumulate p and p*xp[src] -----
__global__ void pass_b_kernel(const void* __restrict__ ei, int E, int ET)
{
    int gt = blockIdx.x * blockDim.x + threadIdx.x;
    int e = gt >> 5;
    int lane = gt & 31;
    if (e >= ET) return;
    int src, dst;
    if (e < E) load_edge(ei, e, E, src, dst);
    else       src = dst = e - E;
    if ((unsigned)src >= NN || (unsigned)dst >= NN) return;  // safety net

    float a0 = g_asrc[src * 2 + 0] + g_adst[dst * 2 + 0];
    float a1 = g_asrc[src * 2 + 1] + g_adst[dst * 2 + 1];
    a0 = a0 > 0.f ? a0 : NEG_SLOPE * a0;
    a1 = a1 > 0.f ? a1 : NEG_SLOPE * a1;
    float p0 = expf(a0 - g_amax[dst * 2 + 0]);
    float p1 = expf(a1 - g_amax[dst * 2 + 1]);

    if (lane == 0) atomicAdd(&g_denom[dst * 2 + 0], p0);
    if (lane == 1) atomicAdd(&g_denom[dst * 2 + 1], p1);

    const float4* xs = (const float4*)(g_xp + (size_t)src * FEAT);
    float4*       ac = (float4*)(g_accum + (size_t)dst * FEAT);

    float4 v0 = xs[lane];
    atomicAdd(&ac[lane],      make_float4(v0.x * p0, v0.y * p0, v0.z * p0, v0.w * p0));
    float4 v1 = xs[lane + 32];
    atomicAdd(&ac[lane + 32], make_float4(v1.x * p1, v1.y * p1, v1.z * p1, v1.w * p1));
}

// ---------------- finalize: accum = accum/denom + bias_g (in place) ---------
__global__ void finalize_kernel(const float* __restrict__ bias_g)
{
    int i = blockIdx.x * blockDim.x + threadIdx.x;
    if (i >= NN * FEAT) return;
    int n = i >> 8;          // /256
    int j = i & 255;
    int h = j >> 7;          // /128
    float d = fmaxf(g_denom[n * HEADS + h], 1e-16f);
    g_accum[i] = g_accum[i] / d + bias_g[j];
}

// ---------------- launch ----------------------------------------------------
extern "C" void kernel_launch(void* const* d_in, const int* in_sizes, int n_in,
                              void* d_out, int out_size)
{
    const float* z       = (const float*)d_in[0];
    const void*  ei      = d_in[1];
    const float* W1      = (const float*)d_in[2];
    const float* b1      = (const float*)d_in[3];
    const float* W2      = (const float*)d_in[4];
    const float* b2      = (const float*)d_in[5];
    const float* Wg      = (const float*)d_in[6];
    const float* att_src = (const float*)d_in[7];
    const float* att_dst = (const float*)d_in[8];
    const float* bias_g  = (const float*)d_in[9];
    const float* W3      = (const float*)d_in[10];
    const float* b3      = (const float*)d_in[11];
    float*       out     = (float*)d_out;

    int E  = in_sizes[1] / 2;
    int ET = E + NN;

    // 0) sniff edge_index dtype
    {
        int nwords = 4096;
        if (nwords > in_sizes[1]) nwords = in_sizes[1];
        detect_kernel<<<(nwords / 2 + 255) / 256, 256>>>((const unsigned int*)ei, nwords);
    }
    // 1) x1 = relu(z @ W1 + b1): [20000,512]x[512,256] -> g_x1
    {
        dim3 grid(HID / 128, (NN + 127) / 128);
        tf32_gemm_kernel<<<grid, 256>>>(z, 0, W1, b1, nullptr, 1, NN, HID, LATENT, 1);
    }
    // 2) x2 = relu(x1 @ W2 + b2): [20000,256]x[256,512] -> g_x2
    {
        dim3 grid((HID * HEADS) / 128, (NN + 127) / 128);
        tf32_gemm_kernel<<<grid, 256>>>(nullptr, 1, W2, b2, nullptr, 2, NN, HID * HEADS, HID, 1);
    }
    // 3) xp = x2 @ Wg: [20000,512]x[512,256] -> g_xp
    {
        dim3 grid(FEAT / 128, (NN + 127) / 128);
        tf32_gemm_kernel<<<grid, 256>>>(nullptr, 2, Wg, nullptr, nullptr, 3, NN, FEAT, HID * HEADS, 0);
    }
    // 4) attention scores
    att_kernel<<<(NN * HEADS + 255) / 256, 256>>>(att_src, att_dst);
    // 5) init accum/amax/denom
    init_kernel<<<(NN * FEAT + 255) / 256, 256>>>();
    // 6) segment max
    pass_a_kernel<<<(ET + 255) / 256, 256>>>(ei, E, ET);
    // 7) accumulate messages (warp per edge)
    {
        long long total = (long long)ET * 32;
        pass_b_kernel<<<(int)((total + 255) / 256), 256>>>(ei, E, ET);
    }
    // 8) normalize + bias_g
    finalize_kernel<<<(NN * FEAT + 255) / 256, 256>>>(bias_g);
    // 9) out = xgat @ W3 + b3: [20000,256]x[256,512] -> d_out
    {
        dim3 grid(512 / 128, (NN + 127) / 128);
        tf32_gemm_kernel<<<grid, 256>>>(nullptr, 4, W3, b3, out, 0, NN, 512, FEAT, 0);
    }
}

// round 14
// speedup vs baseline: 1.8441x; 1.0834x over previous
#include <cuda_runtime.h>
#include <cuda_bf16.h>
#include <math.h>
#include <stdint.h>

// Problem constants (fixed shapes)
#define NN      20000
#define LATENT  512
#define HID     256
#define OUTC    128
#define HEADS   2
#define FEAT    (HEADS*OUTC)   // 256
#define NEG_SLOPE 0.2f

// ---------------- scratch (static device globals; 16B aligned) --------------
__device__ __align__(16) float g_x1[NN * HID];          // relu(z@W1+b1), tf32-rounded
__device__ __align__(16) float g_x2[NN * (HID*HEADS)];  // relu(x1@W2+b2), tf32-rounded
__device__ __align__(16) float g_xp[NN * FEAT];         // x2@Wg (full fp32)
__device__ __align__(16) float g_asrc[NN * HEADS];
__device__ __align__(16) float g_adst[NN * HEADS];
__device__ __align__(16) float g_amax[NN * HEADS];
__device__ __align__(16) float g_denom[NN * HEADS];
__device__ __align__(16) float g_accum[NN * FEAT];      // msg sum; finalized+rounded
__device__ __align__(16) float g_zr[NN * LATENT];       // tf32-rounded z
__device__ __align__(16) float g_wt1[HID * LATENT];         // W1^T [256][512]
__device__ __align__(16) float g_wt2[(HID*HEADS) * HID];    // W2^T [512][256]
__device__ __align__(16) float g_wtg[FEAT * (HID*HEADS)];   // Wg^T [256][512]
__device__ __align__(16) float g_wt3[512 * FEAT];           // W3^T [512][256]

// edge_index dtype flag: 1 = int64, 0 = int32. Monotonic -> deterministic.
__device__ int g_is64 = 1;

__device__ __forceinline__ float* buf_sel(int id) {
    switch (id) {
        case 1: return g_x1;
        case 2: return g_x2;
        case 3: return g_xp;
        case 4: return g_accum;
        case 5: return g_zr;
        case 6: return g_wt1;
        case 7: return g_wt2;
        case 8: return g_wtg;
        case 9: return g_wt3;
    }
    return nullptr;
}

// ---------------- helpers ---------------------------------------------------
__device__ __forceinline__ void atomicMaxF(float* addr, float v) {
    if (v >= 0.0f) atomicMax((int*)addr, __float_as_int(v));
    else           atomicMin((unsigned int*)addr, (unsigned int)__float_as_int(v));
}

__device__ __forceinline__ void load_edge(const void* ei, int e, int E, int& src, int& dst) {
    if (g_is64) {
        const long long* p = (const long long*)ei;
        src = (int)p[e]; dst = (int)p[E + e];
    } else {
        const int* p = (const int*)ei;
        src = p[e]; dst = p[E + e];
    }
}

__device__ __forceinline__ uint32_t f2tf32(float f) {
    uint32_t r;
    asm("cvt.rna.tf32.f32 %0, %1;" : "=r"(r) : "f"(f));
    return r;
}

__device__ __forceinline__ void mma_tf32(float c[4],
                                         const uint32_t a[4],
                                         uint32_t b0, uint32_t b1)
{
    asm volatile(
        "mma.sync.aligned.m16n8k8.row.col.f32.tf32.tf32.f32 "
        "{%0,%1,%2,%3}, {%4,%5,%6,%7}, {%8,%9}, {%0,%1,%2,%3};"
        : "+f"(c[0]), "+f"(c[1]), "+f"(c[2]), "+f"(c[3])
        : "r"(a[0]), "r"(a[1]), "r"(a[2]), "r"(a[3]), "r"(b0), "r"(b1));
}

__device__ __forceinline__ void ldsm4(uint32_t r[4], uint32_t addr) {
    asm volatile("ldmatrix.sync.aligned.m8n8.x4.shared.b16 {%0,%1,%2,%3}, [%4];"
                 : "=r"(r[0]), "=r"(r[1]), "=r"(r[2]), "=r"(r[3]) : "r"(addr));
}

__device__ __forceinline__ void cp16(uint32_t dst, const void* src, int sz) {
    asm volatile("cp.async.cg.shared.global [%0], [%1], 16, %2;"
                 :: "r"(dst), "l"(src), "r"(sz) : "memory");
}

// ---------------- dtype detection: odd 32-bit words all zero => int64 -------
__global__ void detect_kernel(const unsigned int* __restrict__ w, int nwords)
{
    int i = blockIdx.x * blockDim.x + threadIdx.x;
    int odd = 2 * i + 1;
    if (odd < nwords && w[odd] != 0u) g_is64 = 0;
}

// ---------------- weight transpose + tf32 round: Wt[n][k] = rna(W[k][n]) ----
__global__ void transpose_cvt_kernel(const float* __restrict__ W, int dst_id, int K, int N)
{
    __shared__ float t[32][33];
    float* Wt = buf_sel(dst_id);
    int n0 = blockIdx.x * 32, k0 = blockIdx.y * 32;
    int tx = threadIdx.x, ty = threadIdx.y;   // 32 x 8
    #pragma unroll
    for (int r = ty; r < 32; r += 8)
        t[r][tx] = W[(size_t)(k0 + r) * N + n0 + tx];
    __syncthreads();
    #pragma unroll
    for (int r = ty; r < 32; r += 8)
        Wt[(size_t)(n0 + r) * K + k0 + tx] = __uint_as_float(f2tf32(t[tx][r]));
}

// ---------------- round z -> g_zr (tf32 rna) --------------------------------
__global__ void round_z_kernel(const float* __restrict__ z)
{
    int i = blockIdx.x * blockDim.x + threadIdx.x;
    if (i >= NN * LATENT / 4) return;
    float4 v = ((const float4*)z)[i];
    uint4 r;
    r.x = f2tf32(v.x); r.y = f2tf32(v.y); r.z = f2tf32(v.z); r.w = f2tf32(v.w);
    ((uint4*)g_zr)[i] = r;
}

// ---------------- tf32 tensor-core GEMM: C = A[M,K] @ Bt[n][k]^T ------------
// BM=128, BN=128, BK=16; 256 thr = 8 warps (4m x 2n), warp tile 32x64.
// cp.async 3-stage pipeline; ldmatrix.x4 fragments; XOR-swizzled smem.
// Inputs must already be tf32-rounded (weights in transpose, A at producer).
#define PIPE 3
#define STAGE_BYTES 16384   // 8KB A + 8KB B

__global__ void __launch_bounds__(256, 2)
tf32_gemm_kernel(const float* __restrict__ Aext, int a_id, int bt_id,
                 const float* __restrict__ bias,
                 float* __restrict__ Cext, int c_id,
                 int M, int N, int K, int relu, int round_out)
{
    const float* A  = (a_id > 0) ? buf_sel(a_id) : Aext;
    const float* Bt = buf_sel(bt_id);
    float*       C  = (c_id > 0) ? buf_sel(c_id) : Cext;

    __shared__ __align__(16) char smem_raw[PIPE * STAGE_BYTES];
    const uint32_t sm0 = (uint32_t)__cvta_generic_to_shared(smem_raw);

    const int tid  = threadIdx.x;
    const int warp = tid >> 5;
    const int lane = tid & 31;

    const int bm = blockIdx.y * 128;
    const int bn = blockIdx.x * 128;
    const int warp_m = warp >> 1;   // 0..3
    const int warp_n = warp & 1;    // 0..1

    // ldmatrix per-lane row/chunk components
    const int lrowA = lane & 15;
    const int lchA  = lane >> 4;            // 0/1
    const int lrowB = ((lane >> 4) << 3) | (lane & 7);   // 0..15
    const int lchB  = (lane >> 3) & 1;      // 0/1

    // staging mapping: thread covers one row-half (2 chunks of 16B)
    const int srow = tid >> 1;              // 0..127
    const int sc   = (tid & 1) * 2;         // chunk 0 or 2

    const int agrow = bm + srow;
    const int sz_a  = (agrow < M) ? 16 : 0;
    const float* arow_ptr = A + (size_t)(agrow < M ? agrow : M - 1) * K;
    const float* brow_ptr = Bt + (size_t)(bn + srow) * K;
    const uint32_t adst0 = sm0 + srow * 64 + ((sc     ^ ((srow >> 1) & 3)) * 16);
    const uint32_t adst1 = sm0 + srow * 64 + (((sc+1) ^ ((srow >> 1) & 3)) * 16);

    float c[2][8][4];
    #pragma unroll
    for (int mt = 0; mt < 2; mt++)
        #pragma unroll
        for (int nt = 0; nt < 8; nt++)
            #pragma unroll
            for (int i = 0; i < 4; i++) c[mt][nt][i] = 0.0f;

    const int T = K >> 4;

    // stage issue: tile t -> buffer s
    auto stage_issue = [&](int t, int s) {
        const uint32_t off = (uint32_t)(s * STAGE_BYTES);
        const float* asrc = arow_ptr + t * 16 + sc * 4;
        cp16(adst0 + off, asrc,     sz_a);
        cp16(adst1 + off, asrc + 4, sz_a);
        const float* bsrc = brow_ptr + t * 16 + sc * 4;
        cp16(adst0 + off + 8192, bsrc,     16);
        cp16(adst1 + off + 8192, bsrc + 4, 16);
        asm volatile("cp.async.commit_group;" ::: "memory");
    };

    stage_issue(0, 0);
    if (T > 1) stage_issue(1, 1);

    for (int t = 0; t < T; t++) {
        if (t == T - 1) asm volatile("cp.async.wait_group 0;" ::: "memory");
        else            asm volatile("cp.async.wait_group 1;" ::: "memory");
        __syncthreads();
        if (t + 2 < T) stage_issue(t + 2, (t + 2) % PIPE);

        const uint32_t sa = sm0 + (t % PIPE) * STAGE_BYTES;
        const uint32_t sb = sa + 8192;

        #pragma unroll
        for (int kk = 0; kk < 2; kk++) {
            uint32_t a[2][4];
            #pragma unroll
            for (int mt = 0; mt < 2; mt++) {
                int row = warp_m * 32 + mt * 16 + lrowA;
                int swz = (2 * kk + lchA) ^ ((row >> 1) & 3);
                ldsm4(a[mt], sa + row * 64 + swz * 16);
            }
            uint32_t b[4][4];
            #pragma unroll
            for (int ntp = 0; ntp < 4; ntp++) {
                int row = warp_n * 64 + ntp * 16 + lrowB;
                int swz = (2 * kk + lchB) ^ ((row >> 1) & 3);
                ldsm4(b[ntp], sb + row * 64 + swz * 16);
            }
            #pragma unroll
            for (int ntp = 0; ntp < 4; ntp++) {
                #pragma unroll
                for (int half = 0; half < 2; half++) {
                    int nt = ntp * 2 + half;
                    mma_tf32(c[0][nt], a[0], b[ntp][2*half], b[ntp][2*half+1]);
                    mma_tf32(c[1][nt], a[1], b[ntp][2*half], b[ntp][2*half+1]);
                }
            }
        }
    }

    // ---- epilogue
    const int gid = lane >> 2;
    const int tig = lane & 3;
    #pragma unroll
    for (int nt = 0; nt < 8; nt++) {
        int col = bn + warp_n * 64 + nt * 8 + 2 * tig;
        float bb0 = bias ? bias[col]     : 0.0f;
        float bb1 = bias ? bias[col + 1] : 0.0f;
        #pragma unroll
        for (int mt = 0; mt < 2; mt++) {
            int row0 = bm + warp_m * 32 + mt * 16 + gid;
            float v0 = c[mt][nt][0] + bb0;
            float v1 = c[mt][nt][1] + bb1;
            float v2 = c[mt][nt][2] + bb0;
            float v3 = c[mt][nt][3] + bb1;
            if (relu) {
                v0 = fmaxf(v0, 0.f); v1 = fmaxf(v1, 0.f);
                v2 = fmaxf(v2, 0.f); v3 = fmaxf(v3, 0.f);
            }
            if (round_out) {
                v0 = __uint_as_float(f2tf32(v0));
                v1 = __uint_as_float(f2tf32(v1));
                v2 = __uint_as_float(f2tf32(v2));
                v3 = __uint_as_float(f2tf32(v3));
            }
            if (row0 < M)     *(float2*)(C + (size_t)row0 * N + col)       = make_float2(v0, v1);
            if (row0 + 8 < M) *(float2*)(C + (size_t)(row0 + 8) * N + col) = make_float2(v2, v3);
        }
    }
}

// ---------------- attention scores: a_src/a_dst per (node, head) ------------
__global__ void att_kernel(const float* __restrict__ att_src, const float* __restrict__ att_dst)
{
    int i = blockIdx.x * blockDim.x + threadIdx.x;
    if (i >= NN * HEADS) return;
    int n = i >> 1, h = i & 1;
    const float4* row = (const float4*)(g_xp + (size_t)n * FEAT + h * OUTC);
    const float4* ws  = (const float4*)(att_src + h * OUTC);
    const float4* wd  = (const float4*)(att_dst + h * OUTC);
    float s = 0.f, d = 0.f;
    #pragma unroll
    for (int c = 0; c < OUTC / 4; c++) {
        float4 x = row[c], a = ws[c], b = wd[c];
        s += x.x * a.x + x.y * a.y + x.z * a.z + x.w * a.w;
        d += x.x * b.x + x.y * b.y + x.z * b.z + x.w * b.w;
    }
    g_asrc[i] = s;
    g_adst[i] = d;
}

// ---------------- init: amax=-inf-ish, denom=0, accum=0 ---------------------
__global__ void init_kernel()
{
    int i = blockIdx.x * blockDim.x + threadIdx.x;
    if (i < NN * FEAT) g_accum[i] = 0.0f;
    if (i < NN * HEADS) { g_amax[i] = -1e30f; g_denom[i] = 0.0f; }
}

// ---------------- pass A: segment max of leaky_relu(a_src+a_dst) over dst ---
__global__ void pass_a_kernel(const void* __restrict__ ei, int E, int ET)
{
    int e = blockIdx.x * blockDim.x + threadIdx.x;
    if (e >= ET) return;
    int src, dst;
    if (e < E) load_edge(ei, e, E, src, dst);
    else       src = dst = e - E;
    if ((unsigned)src >= NN || (unsigned)dst >= NN) return;  // safety net
    #pragma unroll
    for (int h = 0; h < HEADS; h++) {
        float a = g_asrc[src * HEADS + h] + g_adst[dst * HEADS + h];
        a = a > 0.f ? a : NEG_SLOPE * a;
        atomicMaxF(&g_amax[dst * HEADS + h], a);
    }
}

// ---------------- pass B: one warp per edge; accumulate p and p*xp[src] -----
__global__ void pass_b_kernel(const void* __restrict__ ei, int E, int ET)
{
    int gt = blockIdx.x * blockDim.x + threadIdx.x;
    int e = gt >> 5;
    int lane = gt & 31;
    if (e >= ET) return;
    int src, dst;
    if (e < E) load_edge(ei, e, E, src, dst);
    else       src = dst = e - E;
    if ((unsigned)src >= NN || (unsigned)dst >= NN) return;  // safety net

    float a0 = g_asrc[src * 2 + 0] + g_adst[dst * 2 + 0];
    float a1 = g_asrc[src * 2 + 1] + g_adst[dst * 2 + 1];
    a0 = a0 > 0.f ? a0 : NEG_SLOPE * a0;
    a1 = a1 > 0.f ? a1 : NEG_SLOPE * a1;
    float p0 = expf(a0 - g_amax[dst * 2 + 0]);
    float p1 = expf(a1 - g_amax[dst * 2 + 1]);

    if (lane == 0) atomicAdd(&g_denom[dst * 2 + 0], p0);
    if (lane == 1) atomicAdd(&g_denom[dst * 2 + 1], p1);

    const float4* xs = (const float4*)(g_xp + (size_t)src * FEAT);
    float4*       ac = (float4*)(g_accum + (size_t)dst * FEAT);

    float4 v0 = xs[lane];
    atomicAdd(&ac[lane],      make_float4(v0.x * p0, v0.y * p0, v0.z * p0, v0.w * p0));
    float4 v1 = xs[lane + 32];
    atomicAdd(&ac[lane + 32], make_float4(v1.x * p1, v1.y * p1, v1.z * p1, v1.w * p1));
}

// ---------------- finalize: accum = rna(accum/denom + bias_g) (in place) ----
__global__ void finalize_kernel(const float* __restrict__ bias_g)
{
    int i = blockIdx.x * blockDim.x + threadIdx.x;
    if (i >= NN * FEAT) return;
    int n = i >> 8;          // /256
    int j = i & 255;
    int h = j >> 7;          // /128
    float d = fmaxf(g_denom[n * HEADS + h], 1e-16f);
    float v = g_accum[i] / d + bias_g[j];
    g_accum[i] = __uint_as_float(f2tf32(v));   // feeds GEMM4 A (tf32-rounded)
}

// ---------------- launch ----------------------------------------------------
extern "C" void kernel_launch(void* const* d_in, const int* in_sizes, int n_in,
                              void* d_out, int out_size)
{
    const float* z       = (const float*)d_in[0];
    const void*  ei      = d_in[1];
    const float* W1      = (const float*)d_in[2];
    const float* b1      = (const float*)d_in[3];
    const float* W2      = (const float*)d_in[4];
    const float* b2      = (const float*)d_in[5];
    const float* Wg      = (const float*)d_in[6];
    const float* att_src = (const float*)d_in[7];
    const float* att_dst = (const float*)d_in[8];
    const float* bias_g  = (const float*)d_in[9];
    const float* W3      = (const float*)d_in[10];
    const float* b3      = (const float*)d_in[11];
    float*       out     = (float*)d_out;

    int E  = in_sizes[1] / 2;
    int ET = E + NN;

    // 0) dtype sniff + weight transposes (tf32-rounded) + z rounding
    {
        int nwords = 4096;
        if (nwords > in_sizes[1]) nwords = in_sizes[1];
        detect_kernel<<<(nwords / 2 + 255) / 256, 256>>>((const unsigned int*)ei, nwords);
    }
    {
        dim3 blk(32, 8);
        transpose_cvt_kernel<<<dim3(HID / 32,        LATENT / 32),     blk>>>(W1, 6, LATENT,     HID);
        transpose_cvt_kernel<<<dim3(HID*HEADS / 32,  HID / 32),        blk>>>(W2, 7, HID,        HID*HEADS);
        transpose_cvt_kernel<<<dim3(FEAT / 32,       HID*HEADS / 32),  blk>>>(Wg, 8, HID*HEADS,  FEAT);
        transpose_cvt_kernel<<<dim3(512 / 32,        FEAT / 32),       blk>>>(W3, 9, FEAT,       512);
    }
    round_z_kernel<<<(NN * LATENT / 4 + 255) / 256, 256>>>(z);

    // 1) x1 = relu(zr @ W1 + b1) -> g_x1 (rounded)
    tf32_gemm_kernel<<<dim3(HID / 128, (NN + 127) / 128), 256>>>(
        nullptr, 5, 6, b1, nullptr, 1, NN, HID, LATENT, 1, 1);
    // 2) x2 = relu(x1 @ W2 + b2) -> g_x2 (rounded)
    tf32_gemm_kernel<<<dim3(HID*HEADS / 128, (NN + 127) / 128), 256>>>(
        nullptr, 1, 7, b2, nullptr, 2, NN, HID * HEADS, HID, 1, 1);
    // 3) xp = x2 @ Wg -> g_xp (full fp32)
    tf32_gemm_kernel<<<dim3(FEAT / 128, (NN + 127) / 128), 256>>>(
        nullptr, 2, 8, nullptr, nullptr, 3, NN, FEAT, HID * HEADS, 0, 0);
    // 4) attention scores
    att_kernel<<<(NN * HEADS + 255) / 256, 256>>>(att_src, att_dst);
    // 5) init accum/amax/denom
    init_kernel<<<(NN * FEAT + 255) / 256, 256>>>();
    // 6) segment max
    pass_a_kernel<<<(ET + 255) / 256, 256>>>(ei, E, ET);
    // 7) accumulate messages (warp per edge)
    {
        long long total = (long long)ET * 32;
        pass_b_kernel<<<(int)((total + 255) / 256), 256>>>(ei, E, ET);
    }
    // 8) normalize + bias_g (+ tf32 round for GEMM4)
    finalize_kernel<<<(NN * FEAT + 255) / 256, 256>>>(bias_g);
    // 9) out = xgat @ W3 + b3 -> d_out
    tf32_gemm_kernel<<<dim3(512 / 128, (NN + 127) / 128), 256>>>(
        nullptr, 4, 9, b3, out, 0, NN, 512, FEAT, 0, 0);
}

// round 15
// speedup vs baseline: 2.2089x; 1.1978x over previous
#include <cuda_runtime.h>
#include <cuda_bf16.h>
#include <math.h>
#include <stdint.h>

// Problem constants (fixed shapes)
#define NN      20000
#define LATENT  512
#define HID     256
#define OUTC    128
#define HEADS   2
#define FEAT    (HEADS*OUTC)   // 256
#define NEG_SLOPE 0.2f
#define EMAX    1000000

// ---------------- scratch (static device globals; 16B aligned) --------------
__device__ __align__(16) float g_x1[NN * HID];          // relu(z@W1+b1), tf32-rounded
__device__ __align__(16) float g_x2[NN * (HID*HEADS)];  // relu(x1@W2+b2), tf32-rounded
__device__ __align__(16) float g_xp[NN * FEAT];         // x2@Wg (full fp32)
__device__ __align__(16) float g_asrc[NN * HEADS];
__device__ __align__(16) float g_adst[NN * HEADS];
__device__ __align__(16) float g_accum[NN * FEAT];      // gat output (rounded)
__device__ __align__(16) float g_zr[NN * LATENT];       // tf32-rounded z
__device__ __align__(16) float g_wt1[HID * LATENT];         // W1^T [256][512]
__device__ __align__(16) float g_wt2[(HID*HEADS) * HID];    // W2^T [512][256]
__device__ __align__(16) float g_wtg[FEAT * (HID*HEADS)];   // Wg^T [256][512]
__device__ __align__(16) float g_wt3[512 * FEAT];           // W3^T [512][256]
// CSR scratch
__device__ int g_cnt[NN];        // per-dst in-degree, then reused as cursor
__device__ int g_off[NN + 1];    // CSR offsets
__device__ int g_elist[EMAX];    // src per edge, grouped by dst

// edge_index dtype flag: 1 = int64, 0 = int32. Monotonic -> deterministic.
__device__ int g_is64 = 1;

__device__ __forceinline__ float* buf_sel(int id) {
    switch (id) {
        case 1: return g_x1;
        case 2: return g_x2;
        case 3: return g_xp;
        case 4: return g_accum;
        case 5: return g_zr;
        case 6: return g_wt1;
        case 7: return g_wt2;
        case 8: return g_wtg;
        case 9: return g_wt3;
    }
    return nullptr;
}

// ---------------- helpers ---------------------------------------------------
__device__ __forceinline__ void load_edge(const void* ei, int e, int E, int& src, int& dst) {
    if (g_is64) {
        const long long* p = (const long long*)ei;
        src = (int)p[e]; dst = (int)p[E + e];
    } else {
        const int* p = (const int*)ei;
        src = p[e]; dst = p[E + e];
    }
}

__device__ __forceinline__ uint32_t f2tf32(float f) {
    uint32_t r;
    asm("cvt.rna.tf32.f32 %0, %1;" : "=r"(r) : "f"(f));
    return r;
}

__device__ __forceinline__ void mma_tf32(float c[4],
                                         const uint32_t a[4],
                                         uint32_t b0, uint32_t b1)
{
    asm volatile(
        "mma.sync.aligned.m16n8k8.row.col.f32.tf32.tf32.f32 "
        "{%0,%1,%2,%3}, {%4,%5,%6,%7}, {%8,%9}, {%0,%1,%2,%3};"
        : "+f"(c[0]), "+f"(c[1]), "+f"(c[2]), "+f"(c[3])
        : "r"(a[0]), "r"(a[1]), "r"(a[2]), "r"(a[3]), "r"(b0), "r"(b1));
}

__device__ __forceinline__ void ldsm4(uint32_t r[4], uint32_t addr) {
    asm volatile("ldmatrix.sync.aligned.m8n8.x4.shared.b16 {%0,%1,%2,%3}, [%4];"
                 : "=r"(r[0]), "=r"(r[1]), "=r"(r[2]), "=r"(r[3]) : "r"(addr));
}

__device__ __forceinline__ void cp16(uint32_t dst, const void* src, int sz) {
    asm volatile("cp.async.cg.shared.global [%0], [%1], 16, %2;"
                 :: "r"(dst), "l"(src), "r"(sz) : "memory");
}

__device__ __forceinline__ float lrelu(float a) {
    return a > 0.f ? a : NEG_SLOPE * a;
}

// ---------------- dtype detection: odd 32-bit words all zero => int64 -------
__global__ void detect_kernel(const unsigned int* __restrict__ w, int nwords)
{
    int i = blockIdx.x * blockDim.x + threadIdx.x;
    int odd = 2 * i + 1;
    if (odd < nwords && w[odd] != 0u) g_is64 = 0;
}

// ---------------- weight transpose + tf32 round: Wt[n][k] = rna(W[k][n]) ----
__global__ void transpose_cvt_kernel(const float* __restrict__ W, int dst_id, int K, int N)
{
    __shared__ float t[32][33];
    float* Wt = buf_sel(dst_id);
    int n0 = blockIdx.x * 32, k0 = blockIdx.y * 32;
    int tx = threadIdx.x, ty = threadIdx.y;   // 32 x 8
    #pragma unroll
    for (int r = ty; r < 32; r += 8)
        t[r][tx] = W[(size_t)(k0 + r) * N + n0 + tx];
    __syncthreads();
    #pragma unroll
    for (int r = ty; r < 32; r += 8)
        Wt[(size_t)(n0 + r) * K + k0 + tx] = __uint_as_float(f2tf32(t[tx][r]));
}

// ---------------- round z -> g_zr (tf32 rna) --------------------------------
__global__ void round_z_kernel(const float* __restrict__ z)
{
    int i = blockIdx.x * blockDim.x + threadIdx.x;
    if (i >= NN * LATENT / 4) return;
    float4 v = ((const float4*)z)[i];
    uint4 r;
    r.x = f2tf32(v.x); r.y = f2tf32(v.y); r.z = f2tf32(v.z); r.w = f2tf32(v.w);
    ((uint4*)g_zr)[i] = r;
}

// ---------------- tf32 tensor-core GEMM: C = A[M,K] @ Bt[n][k]^T ------------
#define PIPE 3
#define STAGE_BYTES 16384   // 8KB A + 8KB B

__global__ void __launch_bounds__(256, 2)
tf32_gemm_kernel(const float* __restrict__ Aext, int a_id, int bt_id,
                 const float* __restrict__ bias,
                 float* __restrict__ Cext, int c_id,
                 int M, int N, int K, int relu, int round_out)
{
    const float* A  = (a_id > 0) ? buf_sel(a_id) : Aext;
    const float* Bt = buf_sel(bt_id);
    float*       C  = (c_id > 0) ? buf_sel(c_id) : Cext;

    __shared__ __align__(16) char smem_raw[PIPE * STAGE_BYTES];
    const uint32_t sm0 = (uint32_t)__cvta_generic_to_shared(smem_raw);

    const int tid  = threadIdx.x;
    const int warp = tid >> 5;
    const int lane = tid & 31;

    const int bm = blockIdx.y * 128;
    const int bn = blockIdx.x * 128;
    const int warp_m = warp >> 1;   // 0..3
    const int warp_n = warp & 1;    // 0..1

    const int lrowA = lane & 15;
    const int lchA  = lane >> 4;
    const int lrowB = ((lane >> 4) << 3) | (lane & 7);
    const int lchB  = (lane >> 3) & 1;

    const int srow = tid >> 1;
    const int sc   = (tid & 1) * 2;

    const int agrow = bm + srow;
    const int sz_a  = (agrow < M) ? 16 : 0;
    const float* arow_ptr = A + (size_t)(agrow < M ? agrow : M - 1) * K;
    const float* brow_ptr = Bt + (size_t)(bn + srow) * K;
    const uint32_t adst0 = sm0 + srow * 64 + ((sc     ^ ((srow >> 1) & 3)) * 16);
    const uint32_t adst1 = sm0 + srow * 64 + (((sc+1) ^ ((srow >> 1) & 3)) * 16);

    float c[2][8][4];
    #pragma unroll
    for (int mt = 0; mt < 2; mt++)
        #pragma unroll
        for (int nt = 0; nt < 8; nt++)
            #pragma unroll
            for (int i = 0; i < 4; i++) c[mt][nt][i] = 0.0f;

    const int T = K >> 4;

    auto stage_issue = [&](int t, int s) {
        const uint32_t off = (uint32_t)(s * STAGE_BYTES);
        const float* asrc = arow_ptr + t * 16 + sc * 4;
        cp16(adst0 + off, asrc,     sz_a);
        cp16(adst1 + off, asrc + 4, sz_a);
        const float* bsrc = brow_ptr + t * 16 + sc * 4;
        cp16(adst0 + off + 8192, bsrc,     16);
        cp16(adst1 + off + 8192, bsrc + 4, 16);
        asm volatile("cp.async.commit_group;" ::: "memory");
    };

    stage_issue(0, 0);
    if (T > 1) stage_issue(1, 1);

    for (int t = 0; t < T; t++) {
        if (t == T - 1) asm volatile("cp.async.wait_group 0;" ::: "memory");
        else            asm volatile("cp.async.wait_group 1;" ::: "memory");
        __syncthreads();
        if (t + 2 < T) stage_issue(t + 2, (t + 2) % PIPE);

        const uint32_t sa = sm0 + (t % PIPE) * STAGE_BYTES;
        const uint32_t sb = sa + 8192;

        #pragma unroll
        for (int kk = 0; kk < 2; kk++) {
            uint32_t a[2][4];
            #pragma unroll
            for (int mt = 0; mt < 2; mt++) {
                int row = warp_m * 32 + mt * 16 + lrowA;
                int swz = (2 * kk + lchA) ^ ((row >> 1) & 3);
                ldsm4(a[mt], sa + row * 64 + swz * 16);
            }
            uint32_t b[4][4];
            #pragma unroll
            for (int ntp = 0; ntp < 4; ntp++) {
                int row = warp_n * 64 + ntp * 16 + lrowB;
                int swz = (2 * kk + lchB) ^ ((row >> 1) & 3);
                ldsm4(b[ntp], sb + row * 64 + swz * 16);
            }
            #pragma unroll
            for (int ntp = 0; ntp < 4; ntp++) {
                #pragma unroll
                for (int half = 0; half < 2; half++) {
                    int nt = ntp * 2 + half;
                    mma_tf32(c[0][nt], a[0], b[ntp][2*half], b[ntp][2*half+1]);
                    mma_tf32(c[1][nt], a[1], b[ntp][2*half], b[ntp][2*half+1]);
                }
            }
        }
    }

    const int gid = lane >> 2;
    const int tig = lane & 3;
    #pragma unroll
    for (int nt = 0; nt < 8; nt++) {
        int col = bn + warp_n * 64 + nt * 8 + 2 * tig;
        float bb0 = bias ? bias[col]     : 0.0f;
        float bb1 = bias ? bias[col + 1] : 0.0f;
        #pragma unroll
        for (int mt = 0; mt < 2; mt++) {
            int row0 = bm + warp_m * 32 + mt * 16 + gid;
            float v0 = c[mt][nt][0] + bb0;
            float v1 = c[mt][nt][1] + bb1;
            float v2 = c[mt][nt][2] + bb0;
            float v3 = c[mt][nt][3] + bb1;
            if (relu) {
                v0 = fmaxf(v0, 0.f); v1 = fmaxf(v1, 0.f);
                v2 = fmaxf(v2, 0.f); v3 = fmaxf(v3, 0.f);
            }
            if (round_out) {
                v0 = __uint_as_float(f2tf32(v0));
                v1 = __uint_as_float(f2tf32(v1));
                v2 = __uint_as_float(f2tf32(v2));
                v3 = __uint_as_float(f2tf32(v3));
            }
            if (row0 < M)     *(float2*)(C + (size_t)row0 * N + col)       = make_float2(v0, v1);
            if (row0 + 8 < M) *(float2*)(C + (size_t)(row0 + 8) * N + col) = make_float2(v2, v3);
        }
    }
}

// ---------------- attention scores: a_src/a_dst per (node, head) ------------
__global__ void att_kernel(const float* __restrict__ att_src, const float* __restrict__ att_dst)
{
    int i = blockIdx.x * blockDim.x + threadIdx.x;
    if (i >= NN * HEADS) return;
    int n = i >> 1, h = i & 1;
    const float4* row = (const float4*)(g_xp + (size_t)n * FEAT + h * OUTC);
    const float4* ws  = (const float4*)(att_src + h * OUTC);
    const float4* wd  = (const float4*)(att_dst + h * OUTC);
    float s = 0.f, d = 0.f;
    #pragma unroll
    for (int c = 0; c < OUTC / 4; c++) {
        float4 x = row[c], a = ws[c], b = wd[c];
        s += x.x * a.x + x.y * a.y + x.z * a.z + x.w * a.w;
        d += x.x * b.x + x.y * b.y + x.z * b.z + x.w * b.w;
    }
    g_asrc[i] = s;
    g_adst[i] = d;
}

// ---------------- CSR build --------------------------------------------------
__global__ void zero_cnt_kernel()
{
    int i = blockIdx.x * blockDim.x + threadIdx.x;
    if (i < NN) g_cnt[i] = 0;
}

__global__ void count_kernel(const void* __restrict__ ei, int E)
{
    int e = blockIdx.x * blockDim.x + threadIdx.x;
    if (e >= E) return;
    int src, dst;
    load_edge(ei, e, E, src, dst);
    if ((unsigned)dst >= NN || (unsigned)src >= NN) return;
    atomicAdd(&g_cnt[dst], 1);
}

// single block, 1024 threads, 20 elems each: exclusive scan of g_cnt -> g_off
__global__ void scan_kernel()
{
    __shared__ int sbuf[1024];
    const int CH = 20;
    int t = threadIdx.x;
    int base = t * CH;
    int local[CH];
    int s = 0;
    #pragma unroll
    for (int i = 0; i < CH; i++) {
        int idx = base + i;
        local[i] = s;
        s += (idx < NN) ? g_cnt[idx] : 0;
    }
    sbuf[t] = s;
    __syncthreads();
    for (int o = 1; o < 1024; o <<= 1) {
        int v = (t >= o) ? sbuf[t - o] : 0;
        __syncthreads();
        sbuf[t] += v;
        __syncthreads();
    }
    int excl = (t == 0) ? 0 : sbuf[t - 1];
    #pragma unroll
    for (int i = 0; i < CH; i++) {
        int idx = base + i;
        if (idx < NN) {
            int o = excl + local[i];
            g_off[idx] = o;
            g_cnt[idx] = o;    // reuse as scatter cursor
        }
    }
    if (t == 1023) g_off[NN] = sbuf[1023];
}

__global__ void scatter_kernel(const void* __restrict__ ei, int E)
{
    int e = blockIdx.x * blockDim.x + threadIdx.x;
    if (e >= E) return;
    int src, dst;
    load_edge(ei, e, E, src, dst);
    if ((unsigned)dst >= NN || (unsigned)src >= NN) return;
    int pos = atomicAdd(&g_cnt[dst], 1);
    if (pos < EMAX) g_elist[pos] = src;
}

// ---------------- aggregate: one warp per node (exact softmax, no atomics) --
__global__ void __launch_bounds__(256)
agg_kernel(const float* __restrict__ bias_g)
{
    int warp_g = (blockIdx.x * blockDim.x + threadIdx.x) >> 5;
    int lane = threadIdx.x & 31;
    if (warp_g >= NN) return;
    const int n = warp_g;

    const float adst0 = g_adst[n * 2 + 0];
    const float adst1 = g_adst[n * 2 + 1];
    const int start = g_off[n];
    const int end   = g_off[n + 1];

    // ---- pass 1: segment max (incl. self loop), lane-strided + shfl reduce
    float m0 = lrelu(g_asrc[n * 2 + 0] + adst0);
    float m1 = lrelu(g_asrc[n * 2 + 1] + adst1);
    for (int i = start + lane; i < end; i += 32) {
        int src = g_elist[i];
        m0 = fmaxf(m0, lrelu(g_asrc[src * 2 + 0] + adst0));
        m1 = fmaxf(m1, lrelu(g_asrc[src * 2 + 1] + adst1));
    }
    #pragma unroll
    for (int o = 16; o > 0; o >>= 1) {
        m0 = fmaxf(m0, __shfl_xor_sync(0xffffffffu, m0, o));
        m1 = fmaxf(m1, __shfl_xor_sync(0xffffffffu, m1, o));
    }

    // ---- pass 2: exp + weighted accumulate (whole warp per edge)
    const float4* xp4 = (const float4*)g_xp;
    float4 acc0 = make_float4(0.f, 0.f, 0.f, 0.f);
    float4 acc1 = make_float4(0.f, 0.f, 0.f, 0.f);
    float d0 = 0.f, d1 = 0.f;

    // self loop
    {
        float p0 = expf(lrelu(g_asrc[n * 2 + 0] + adst0) - m0);
        float p1 = expf(lrelu(g_asrc[n * 2 + 1] + adst1) - m1);
        float4 v0 = xp4[(size_t)n * 64 + lane];
        float4 v1 = xp4[(size_t)n * 64 + lane + 32];
        acc0.x += v0.x * p0; acc0.y += v0.y * p0; acc0.z += v0.z * p0; acc0.w += v0.w * p0;
        acc1.x += v1.x * p1; acc1.y += v1.y * p1; acc1.z += v1.z * p1; acc1.w += v1.w * p1;
        d0 += p0; d1 += p1;
    }

    int i = start;
    for (; i + 2 <= end; i += 2) {
        int sA = g_elist[i];
        int sB = g_elist[i + 1];
        float pA0 = expf(lrelu(g_asrc[sA * 2 + 0] + adst0) - m0);
        float pA1 = expf(lrelu(g_asrc[sA * 2 + 1] + adst1) - m1);
        float pB0 = expf(lrelu(g_asrc[sB * 2 + 0] + adst0) - m0);
        float pB1 = expf(lrelu(g_asrc[sB * 2 + 1] + adst1) - m1);
        float4 vA0 = xp4[(size_t)sA * 64 + lane];
        float4 vA1 = xp4[(size_t)sA * 64 + lane + 32];
        float4 vB0 = xp4[(size_t)sB * 64 + lane];
        float4 vB1 = xp4[(size_t)sB * 64 + lane + 32];
        acc0.x += vA0.x * pA0 + vB0.x * pB0;
        acc0.y += vA0.y * pA0 + vB0.y * pB0;
        acc0.z += vA0.z * pA0 + vB0.z * pB0;
        acc0.w += vA0.w * pA0 + vB0.w * pB0;
        acc1.x += vA1.x * pA1 + vB1.x * pB1;
        acc1.y += vA1.y * pA1 + vB1.y * pB1;
        acc1.z += vA1.z * pA1 + vB1.z * pB1;
        acc1.w += vA1.w * pA1 + vB1.w * pB1;
        d0 += pA0 + pB0; d1 += pA1 + pB1;
    }
    if (i < end) {
        int s = g_elist[i];
        float p0 = expf(lrelu(g_asrc[s * 2 + 0] + adst0) - m0);
        float p1 = expf(lrelu(g_asrc[s * 2 + 1] + adst1) - m1);
        float4 v0 = xp4[(size_t)s * 64 + lane];
        float4 v1 = xp4[(size_t)s * 64 + lane + 32];
        acc0.x += v0.x * p0; acc0.y += v0.y * p0; acc0.z += v0.z * p0; acc0.w += v0.w * p0;
        acc1.x += v1.x * p1; acc1.y += v1.y * p1; acc1.z += v1.z * p1; acc1.w += v1.w * p1;
        d0 += p0; d1 += p1;
    }

    // ---- finalize: /denom + bias_g, tf32 round, store
    d0 = fmaxf(d0, 1e-16f); d1 = fmaxf(d1, 1e-16f);
    const float4* bg4 = (const float4*)bias_g;
    float4 b0 = bg4[lane], b1 = bg4[lane + 32];
    uint4 r0, r1;
    r0.x = f2tf32(acc0.x / d0 + b0.x); r0.y = f2tf32(acc0.y / d0 + b0.y);
    r0.z = f2tf32(acc0.z / d0 + b0.z); r0.w = f2tf32(acc0.w / d0 + b0.w);
    r1.x = f2tf32(acc1.x / d1 + b1.x); r1.y = f2tf32(acc1.y / d1 + b1.y);
    r1.z = f2tf32(acc1.z / d1 + b1.z); r1.w = f2tf32(acc1.w / d1 + b1.w);
    ((uint4*)g_accum)[(size_t)n * 64 + lane]      = r0;
    ((uint4*)g_accum)[(size_t)n * 64 + lane + 32] = r1;
}

// ---------------- launch ----------------------------------------------------
extern "C" void kernel_launch(void* const* d_in, const int* in_sizes, int n_in,
                              void* d_out, int out_size)
{
    const float* z       = (const float*)d_in[0];
    const void*  ei      = d_in[1];
    const float* W1      = (const float*)d_in[2];
    const float* b1      = (const float*)d_in[3];
    const float* W2      = (const float*)d_in[4];
    const float* b2      = (const float*)d_in[5];
    const float* Wg      = (const float*)d_in[6];
    const float* att_src = (const float*)d_in[7];
    const float* att_dst = (const float*)d_in[8];
    const float* bias_g  = (const float*)d_in[9];
    const float* W3      = (const float*)d_in[10];
    const float* b3      = (const float*)d_in[11];
    float*       out     = (float*)d_out;

    int E = in_sizes[1] / 2;

    // 0) dtype sniff + weight transposes (tf32-rounded) + z rounding
    {
        int nwords = 4096;
        if (nwords > in_sizes[1]) nwords = in_sizes[1];
        detect_kernel<<<(nwords / 2 + 255) / 256, 256>>>((const unsigned int*)ei, nwords);
    }
    {
        dim3 blk(32, 8);
        transpose_cvt_kernel<<<dim3(HID / 32,        LATENT / 32),     blk>>>(W1, 6, LATENT,     HID);
        transpose_cvt_kernel<<<dim3(HID*HEADS / 32,  HID / 32),        blk>>>(W2, 7, HID,        HID*HEADS);
        transpose_cvt_kernel<<<dim3(FEAT / 32,       HID*HEADS / 32),  blk>>>(Wg, 8, HID*HEADS,  FEAT);
        transpose_cvt_kernel<<<dim3(512 / 32,        FEAT / 32),       blk>>>(W3, 9, FEAT,       512);
    }
    round_z_kernel<<<(NN * LATENT / 4 + 255) / 256, 256>>>(z);

    // CSR build (overlaps conceptually with GEMMs in the graph's stream order)
    zero_cnt_kernel<<<(NN + 255) / 256, 256>>>();
    count_kernel<<<(E + 255) / 256, 256>>>(ei, E);
    scan_kernel<<<1, 1024>>>();
    scatter_kernel<<<(E + 255) / 256, 256>>>(ei, E);

    // 1) x1 = relu(zr @ W1 + b1) -> g_x1 (rounded)
    tf32_gemm_kernel<<<dim3(HID / 128, (NN + 127) / 128), 256>>>(
        nullptr, 5, 6, b1, nullptr, 1, NN, HID, LATENT, 1, 1);
    // 2) x2 = relu(x1 @ W2 + b2) -> g_x2 (rounded)
    tf32_gemm_kernel<<<dim3(HID*HEADS / 128, (NN + 127) / 128), 256>>>(
        nullptr, 1, 7, b2, nullptr, 2, NN, HID * HEADS, HID, 1, 1);
    // 3) xp = x2 @ Wg -> g_xp (full fp32)
    tf32_gemm_kernel<<<dim3(FEAT / 128, (NN + 127) / 128), 256>>>(
        nullptr, 2, 8, nullptr, nullptr, 3, NN, FEAT, HID * HEADS, 0, 0);
    // 4) attention scores
    att_kernel<<<(NN * HEADS + 255) / 256, 256>>>(att_src, att_dst);
    // 5) GAT aggregate (exact softmax, register accumulation, no atomics)
    agg_kernel<<<(NN * 32 + 255) / 256, 256>>>(bias_g);
    // 6) out = xgat @ W3 + b3 -> d_out
    tf32_gemm_kernel<<<dim3(512 / 128, (NN + 127) / 128), 256>>>(
        nullptr, 4, 9, b3, out, 0, NN, 512, FEAT, 0, 0);
}

// round 17
// speedup vs baseline: 2.2874x; 1.0355x over previous
#include <cuda_runtime.h>
#include <cuda_bf16.h>
#include <math.h>
#include <stdint.h>

// Problem constants (fixed shapes)
#define NN      20000
#define LATENT  512
#define HID     256
#define OUTC    128
#define HEADS   2
#define FEAT    (HEADS*OUTC)   // 256
#define NEG_SLOPE 0.2f
#define EMAX    1000000

// ---------------- scratch (static device globals; 16B aligned) --------------
__device__ __align__(16) float g_x1[NN * HID];          // relu(z@W1+b1), tf32-rounded
__device__ __align__(16) float g_x2[NN * (HID*HEADS)];  // relu(x1@W2+b2), tf32-rounded
__device__ __align__(16) float g_xp[NN * FEAT];         // x2@Wg (full fp32)
__device__ __align__(16) float g_asrc[NN * HEADS];
__device__ __align__(16) float g_adst[NN * HEADS];
__device__ __align__(16) float g_accum[NN * FEAT];      // gat output (rounded)
__device__ __align__(16) float g_zr[NN * LATENT];       // tf32-rounded z
__device__ __align__(16) float g_wt1[HID * LATENT];         // W1^T [256][512]
__device__ __align__(16) float g_wt2[(HID*HEADS) * HID];    // W2^T [512][256]
__device__ __align__(16) float g_wtg[FEAT * (HID*HEADS)];   // Wg^T [256][512]
__device__ __align__(16) float g_wt3[512 * FEAT];           // W3^T [512][256]
// CSR scratch
__device__ int g_cnt[NN];
__device__ int g_off[NN + 1];
__device__ int g_elist[EMAX];

__device__ int g_is64 = 1;

__device__ __forceinline__ float* buf_sel(int id) {
    switch (id) {
        case 1: return g_x1;
        case 2: return g_x2;
        case 3: return g_xp;
        case 4: return g_accum;
        case 5: return g_zr;
        case 6: return g_wt1;
        case 7: return g_wt2;
        case 8: return g_wtg;
        case 9: return g_wt3;
    }
    return nullptr;
}

// ---------------- helpers ---------------------------------------------------
__device__ __forceinline__ void load_edge(const void* ei, int e, int E, int& src, int& dst) {
    if (g_is64) {
        const long long* p = (const long long*)ei;
        src = (int)p[e]; dst = (int)p[E + e];
    } else {
        const int* p = (const int*)ei;
        src = p[e]; dst = p[E + e];
    }
}

__device__ __forceinline__ uint32_t f2tf32(float f) {
    uint32_t r;
    asm("cvt.rna.tf32.f32 %0, %1;" : "=r"(r) : "f"(f));
    return r;
}

__device__ __forceinline__ void mma_tf32(float c[4],
                                         const uint32_t a[4],
                                         uint32_t b0, uint32_t b1)
{
    asm volatile(
        "mma.sync.aligned.m16n8k8.row.col.f32.tf32.tf32.f32 "
        "{%0,%1,%2,%3}, {%4,%5,%6,%7}, {%8,%9}, {%0,%1,%2,%3};"
        : "+f"(c[0]), "+f"(c[1]), "+f"(c[2]), "+f"(c[3])
        : "r"(a[0]), "r"(a[1]), "r"(a[2]), "r"(a[3]), "r"(b0), "r"(b1));
}

__device__ __forceinline__ void ldsm4(uint32_t r[4], uint32_t addr) {
    asm volatile("ldmatrix.sync.aligned.m8n8.x4.shared.b16 {%0,%1,%2,%3}, [%4];"
                 : "=r"(r[0]), "=r"(r[1]), "=r"(r[2]), "=r"(r[3]) : "r"(addr));
}

__device__ __forceinline__ void cp16(uint32_t dst, const void* src, int sz) {
    asm volatile("cp.async.cg.shared.global [%0], [%1], 16, %2;"
                 :: "r"(dst), "l"(src), "r"(sz) : "memory");
}

__device__ __forceinline__ float lrelu(float a) {
    return a > 0.f ? a : NEG_SLOPE * a;
}

// ---------------- dtype detection: odd 32-bit words all zero => int64 -------
__global__ void detect_kernel(const unsigned int* __restrict__ w, int nwords)
{
    int i = blockIdx.x * blockDim.x + threadIdx.x;
    int odd = 2 * i + 1;
    if (odd < nwords && w[odd] != 0u) g_is64 = 0;
}

// ---------------- fused prologue: 4 transposes + round_z + zero_cnt ---------
// blocks [0,512): weight transposes (128 each); [512,10512): round_z;
// [10512,10591): zero g_cnt.
__device__ __forceinline__ void transpose_tile(const float* __restrict__ W, float* __restrict__ Wt,
                                               int K, int N, int rb, int tid)
{
    __shared__ float t[32][33];
    int gx = N / 32;
    int n0 = (rb % gx) * 32, k0 = (rb / gx) * 32;
    int tx = tid & 31, ty = tid >> 5;   // 32 x 8
    #pragma unroll
    for (int r = ty; r < 32; r += 8)
        t[r][tx] = W[(size_t)(k0 + r) * N + n0 + tx];
    __syncthreads();
    #pragma unroll
    for (int r = ty; r < 32; r += 8)
        Wt[(size_t)(n0 + r) * K + k0 + tx] = __uint_as_float(f2tf32(t[tx][r]));
}

__global__ void prologue_kernel(const float* __restrict__ W1, const float* __restrict__ W2,
                                const float* __restrict__ Wg, const float* __restrict__ W3,
                                const float* __restrict__ z)
{
    int b = blockIdx.x;
    int tid = threadIdx.x;
    if (b < 512) {
        int which = b >> 7, rb = b & 127;
        if      (which == 0) transpose_tile(W1, g_wt1, LATENT,    HID,       rb, tid);
        else if (which == 1) transpose_tile(W2, g_wt2, HID,       HID*HEADS, rb, tid);
        else if (which == 2) transpose_tile(Wg, g_wtg, HID*HEADS, FEAT,      rb, tid);
        else                 transpose_tile(W3, g_wt3, FEAT,      512,       rb, tid);
    } else if (b < 10512) {
        int i = (b - 512) * 256 + tid;
        if (i < NN * LATENT / 4) {
            float4 v = ((const float4*)z)[i];
            uint4 r;
            r.x = f2tf32(v.x); r.y = f2tf32(v.y); r.z = f2tf32(v.z); r.w = f2tf32(v.w);
            ((uint4*)g_zr)[i] = r;
        }
    } else {
        int i = (b - 10512) * 256 + tid;
        if (i < NN) g_cnt[i] = 0;
    }
}

// ---------------- tf32 tensor-core GEMM: C = A[M,K] @ Bt[n][k]^T ------------
// BM=128, BN=128, BK=32; 256 thr = 8 warps (4m x 2n), warp tile 32x64.
// cp.async 3-stage pipeline (dynamic smem, 96KB), ldmatrix.x4, XOR swizzle.
// 128B rows, 8 chunks of 16B, phys chunk = c ^ (row & 7).
#define PIPE 3
#define STAGE_BYTES 32768   // 16KB A + 16KB B

__global__ void __launch_bounds__(256, 2)
tf32_gemm_kernel(const float* __restrict__ Aext, int a_id, int bt_id,
                 const float* __restrict__ bias,
                 float* __restrict__ Cext, int c_id,
                 int M, int N, int K, int relu, int round_out)
{
    const float* A  = (a_id > 0) ? buf_sel(a_id) : Aext;
    const float* Bt = buf_sel(bt_id);
    float*       C  = (c_id > 0) ? buf_sel(c_id) : Cext;

    extern __shared__ __align__(16) char smem_raw[];
    const uint32_t sm0 = (uint32_t)__cvta_generic_to_shared(smem_raw);

    const int tid  = threadIdx.x;
    const int warp = tid >> 5;
    const int lane = tid & 31;

    const int bm = blockIdx.y * 128;
    const int bn = blockIdx.x * 128;
    const int warp_m = warp >> 1;   // 0..3
    const int warp_n = warp & 1;    // 0..1

    const int lrowA = lane & 15;
    const int lchA  = lane >> 4;
    const int lrowB = ((lane >> 4) << 3) | (lane & 7);
    const int lchB  = (lane >> 3) & 1;

    // staging: thread covers half a row = 64B = 4 chunks
    const int srow = tid >> 1;              // 0..127
    const int shalf = tid & 1;              // 0/1 -> chunks 4h..4h+3

    const int agrow = bm + srow;
    const int sz_a  = (agrow < M) ? 16 : 0;
    const float* arow_ptr = A + (size_t)(agrow < M ? agrow : M - 1) * K + shalf * 16;
    const float* brow_ptr = Bt + (size_t)(bn + srow) * K + shalf * 16;
    // swizzled dst offsets for the 4 chunks
    uint32_t adst[4];
    #pragma unroll
    for (int i = 0; i < 4; i++) {
        int c = shalf * 4 + i;
        adst[i] = sm0 + srow * 128 + ((c ^ (srow & 7)) * 16);
    }

    float c[2][8][4];
    #pragma unroll
    for (int mt = 0; mt < 2; mt++)
        #pragma unroll
        for (int nt = 0; nt < 8; nt++)
            #pragma unroll
            for (int i = 0; i < 4; i++) c[mt][nt][i] = 0.0f;

    const int T = K >> 5;   // BK=32 stages

    auto stage_issue = [&](int t, int s) {
        const uint32_t off = (uint32_t)(s * STAGE_BYTES);
        const float* asrc = arow_ptr + t * 32;
        const float* bsrc = brow_ptr + t * 32;
        #pragma unroll
        for (int i = 0; i < 4; i++) cp16(adst[i] + off, asrc + i * 4, sz_a);
        #pragma unroll
        for (int i = 0; i < 4; i++) cp16(adst[i] + off + 16384, bsrc + i * 4, 16);
        asm volatile("cp.async.commit_group;" ::: "memory");
    };

    stage_issue(0, 0);
    if (T > 1) stage_issue(1, 1);

    for (int t = 0; t < T; t++) {
        if (t == T - 1) asm volatile("cp.async.wait_group 0;" ::: "memory");
        else            asm volatile("cp.async.wait_group 1;" ::: "memory");
        __syncthreads();
        if (t + 2 < T) stage_issue(t + 2, (t + 2) % PIPE);

        const uint32_t sa = sm0 + (t % PIPE) * STAGE_BYTES;
        const uint32_t sb = sa + 16384;

        #pragma unroll
        for (int kk = 0; kk < 4; kk++) {
            uint32_t a[2][4];
            #pragma unroll
            for (int mt = 0; mt < 2; mt++) {
                int row = warp_m * 32 + mt * 16 + lrowA;
                int swz = (2 * kk + lchA) ^ (row & 7);
                ldsm4(a[mt], sa + row * 128 + swz * 16);
            }
            uint32_t b[4][4];
            #pragma unroll
            for (int ntp = 0; ntp < 4; ntp++) {
                int row = warp_n * 64 + ntp * 16 + lrowB;
                int swz = (2 * kk + lchB) ^ (row & 7);
                ldsm4(b[ntp], sb + row * 128 + swz * 16);
            }
            #pragma unroll
            for (int ntp = 0; ntp < 4; ntp++) {
                #pragma unroll
                for (int half = 0; half < 2; half++) {
                    int nt = ntp * 2 + half;
                    mma_tf32(c[0][nt], a[0], b[ntp][2*half], b[ntp][2*half+1]);
                    mma_tf32(c[1][nt], a[1], b[ntp][2*half], b[ntp][2*half+1]);
                }
            }
        }
        __syncthreads();
    }

    const int gid = lane >> 2;
    const int tig = lane & 3;
    #pragma unroll
    for (int nt = 0; nt < 8; nt++) {
        int col = bn + warp_n * 64 + nt * 8 + 2 * tig;
        float bb0 = bias ? bias[col]     : 0.0f;
        float bb1 = bias ? bias[col + 1] : 0.0f;
        #pragma unroll
        for (int mt = 0; mt < 2; mt++) {
            int row0 = bm + warp_m * 32 + mt * 16 + gid;
            float v0 = c[mt][nt][0] + bb0;
            float v1 = c[mt][nt][1] + bb1;
            float v2 = c[mt][nt][2] + bb0;
            float v3 = c[mt][nt][3] + bb1;
            if (relu) {
                v0 = fmaxf(v0, 0.f); v1 = fmaxf(v1, 0.f);
                v2 = fmaxf(v2, 0.f); v3 = fmaxf(v3, 0.f);
            }
            if (round_out) {
                v0 = __uint_as_float(f2tf32(v0));
                v1 = __uint_as_float(f2tf32(v1));
                v2 = __uint_as_float(f2tf32(v2));
                v3 = __uint_as_float(f2tf32(v3));
            }
            if (row0 < M)     *(float2*)(C + (size_t)row0 * N + col)       = make_float2(v0, v1);
            if (row0 + 8 < M) *(float2*)(C + (size_t)(row0 + 8) * N + col) = make_float2(v2, v3);
        }
    }
}

// ---------------- attention scores: a_src/a_dst per (node, head) ------------
__global__ void att_kernel(const float* __restrict__ att_src, const float* __restrict__ att_dst)
{
    int i = blockIdx.x * blockDim.x + threadIdx.x;
    if (i >= NN * HEADS) return;
    int n = i >> 1, h = i & 1;
    const float4* row = (const float4*)(g_xp + (size_t)n * FEAT + h * OUTC);
    const float4* ws  = (const float4*)(att_src + h * OUTC);
    const float4* wd  = (const float4*)(att_dst + h * OUTC);
    float s = 0.f, d = 0.f;
    #pragma unroll
    for (int c = 0; c < OUTC / 4; c++) {
        float4 x = row[c], a = ws[c], b = wd[c];
        s += x.x * a.x + x.y * a.y + x.z * a.z + x.w * a.w;
        d += x.x * b.x + x.y * b.y + x.z * b.z + x.w * b.w;
    }
    g_asrc[i] = s;
    g_adst[i] = d;
}

// ---------------- CSR build --------------------------------------------------
__global__ void count_kernel(const void* __restrict__ ei, int E)
{
    int e = blockIdx.x * blockDim.x + threadIdx.x;
    if (e >= E) return;
    int src, dst;
    load_edge(ei, e, E, src, dst);
    if ((unsigned)dst >= NN || (unsigned)src >= NN) return;
    atomicAdd(&g_cnt[dst], 1);
}

__global__ void scan_kernel()
{
    __shared__ int sbuf[1024];
    const int CH = 20;
    int t = threadIdx.x;
    int base = t * CH;
    int local[CH];
    int s = 0;
    #pragma unroll
    for (int i = 0; i < CH; i++) {
        int idx = base + i;
        local[i] = s;
        s += (idx < NN) ? g_cnt[idx] : 0;
    }
    sbuf[t] = s;
    __syncthreads();
    for (int o = 1; o < 1024; o <<= 1) {
        int v = (t >= o) ? sbuf[t - o] : 0;
        __syncthreads();
        sbuf[t] += v;
        __syncthreads();
    }
    int excl = (t == 0) ? 0 : sbuf[t - 1];
    #pragma unroll
    for (int i = 0; i < CH; i++) {
        int idx = base + i;
        if (idx < NN) {
            int o = excl + local[i];
            g_off[idx] = o;
            g_cnt[idx] = o;
        }
    }
    if (t == 1023) g_off[NN] = sbuf[1023];
}

__global__ void scatter_kernel(const void* __restrict__ ei, int E)
{
    int e = blockIdx.x * blockDim.x + threadIdx.x;
    if (e >= E) return;
    int src, dst;
    load_edge(ei, e, E, src, dst);
    if ((unsigned)dst >= NN || (unsigned)src >= NN) return;
    int pos = atomicAdd(&g_cnt[dst], 1);
    if (pos < EMAX) g_elist[pos] = src;
}

// ---------------- aggregate: one warp per node (exact softmax, no atomics) --
__global__ void __launch_bounds__(256)
agg_kernel(const float* __restrict__ bias_g)
{
    int warp_g = (blockIdx.x * blockDim.x + threadIdx.x) >> 5;
    int lane = threadIdx.x & 31;
    if (warp_g >= NN) return;
    const int n = warp_g;

    const float adst0 = g_adst[n * 2 + 0];
    const float adst1 = g_adst[n * 2 + 1];
    const int start = g_off[n];
    const int end   = g_off[n + 1];

    float m0 = lrelu(g_asrc[n * 2 + 0] + adst0);
    float m1 = lrelu(g_asrc[n * 2 + 1] + adst1);
    for (int i = start + lane; i < end; i += 32) {
        int src = g_elist[i];
        m0 = fmaxf(m0, lrelu(g_asrc[src * 2 + 0] + adst0));
        m1 = fmaxf(m1, lrelu(g_asrc[src * 2 + 1] + adst1));
    }
    #pragma unroll
    for (int o = 16; o > 0; o >>= 1) {
        m0 = fmaxf(m0, __shfl_xor_sync(0xffffffffu, m0, o));
        m1 = fmaxf(m1, __shfl_xor_sync(0xffffffffu, m1, o));
    }

    const float4* xp4 = (const float4*)g_xp;
    float4 acc0 = make_float4(0.f, 0.f, 0.f, 0.f);
    float4 acc1 = make_float4(0.f, 0.f, 0.f, 0.f);
    float d0 = 0.f, d1 = 0.f;

    {
        float p0 = expf(lrelu(g_asrc[n * 2 + 0] + adst0) - m0);
        float p1 = expf(lrelu(g_asrc[n * 2 + 1] + adst1) - m1);
        float4 v0 = xp4[(size_t)n * 64 + lane];
        float4 v1 = xp4[(size_t)n * 64 + lane + 32];
        acc0.x += v0.x * p0; acc0.y += v0.y * p0; acc0.z += v0.z * p0; acc0.w += v0.w * p0;
        acc1.x += v1.x * p1; acc1.y += v1.y * p1; acc1.z += v1.z * p1; acc1.w += v1.w * p1;
        d0 += p0; d1 += p1;
    }

    int i = start;
    for (; i + 2 <= end; i += 2) {
        int sA = g_elist[i];
        int sB = g_elist[i + 1];
        float pA0 = expf(lrelu(g_asrc[sA * 2 + 0] + adst0) - m0);
        float pA1 = expf(lrelu(g_asrc[sA * 2 + 1] + adst1) - m1);
        float pB0 = expf(lrelu(g_asrc[sB * 2 + 0] + adst0) - m0);
        float pB1 = expf(lrelu(g_asrc[sB * 2 + 1] + adst1) - m1);
        float4 vA0 = xp4[(size_t)sA * 64 + lane];
        float4 vA1 = xp4[(size_t)sA * 64 + lane + 32];
        float4 vB0 = xp4[(size_t)sB * 64 + lane];
        float4 vB1 = xp4[(size_t)sB * 64 + lane + 32];
        acc0.x += vA0.x * pA0 + vB0.x * pB0;
        acc0.y += vA0.y * pA0 + vB0.y * pB0;
        acc0.z += vA0.z * pA0 + vB0.z * pB0;
        acc0.w += vA0.w * pA0 + vB0.w * pB0;
        acc1.x += vA1.x * pA1 + vB1.x * pB1;
        acc1.y += vA1.y * pA1 + vB1.y * pB1;
        acc1.z += vA1.z * pA1 + vB1.z * pB1;
        acc1.w += vA1.w * pA1 + vB1.w * pB1;
        d0 += pA0 + pB0; d1 += pA1 + pB1;
    }
    if (i < end) {
        int s = g_elist[i];
        float p0 = expf(lrelu(g_asrc[s * 2 + 0] + adst0) - m0);
        float p1 = expf(lrelu(g_asrc[s * 2 + 1] + adst1) - m1);
        float4 v0 = xp4[(size_t)s * 64 + lane];
        float4 v1 = xp4[(size_t)s * 64 + lane + 32];
        acc0.x += v0.x * p0; acc0.y += v0.y * p0; acc0.z += v0.z * p0; acc0.w += v0.w * p0;
        acc1.x += v1.x * p1; acc1.y += v1.y * p1; acc1.z += v1.z * p1; acc1.w += v1.w * p1;
        d0 += p0; d1 += p1;
    }

    d0 = fmaxf(d0, 1e-16f); d1 = fmaxf(d1, 1e-16f);
    const float4* bg4 = (const float4*)bias_g;
    float4 b0 = bg4[lane], b1 = bg4[lane + 32];
    uint4 r0, r1;
    r0.x = f2tf32(acc0.x / d0 + b0.x); r0.y = f2tf32(acc0.y / d0 + b0.y);
    r0.z = f2tf32(acc0.z / d0 + b0.z); r0.w = f2tf32(acc0.w / d0 + b0.w);
    r1.x = f2tf32(acc1.x / d1 + b1.x); r1.y = f2tf32(acc1.y / d1 + b1.y);
    r1.z = f2tf32(acc1.z / d1 + b1.z); r1.w = f2tf32(acc1.w / d1 + b1.w);
    ((uint4*)g_accum)[(size_t)n * 64 + lane]      = r0;
    ((uint4*)g_accum)[(size_t)n * 64 + lane + 32] = r1;
}

// ---------------- launch ----------------------------------------------------
extern "C" void kernel_launch(void* const* d_in, const int* in_sizes, int n_in,
                              void* d_out, int out_size)
{
    const float* z       = (const float*)d_in[0];
    const void*  ei      = d_in[1];
    const float* W1      = (const float*)d_in[2];
    const float* b1      = (const float*)d_in[3];
    const float* W2      = (const float*)d_in[4];
    const float* b2      = (const float*)d_in[5];
    const float* Wg      = (const float*)d_in[6];
    const float* att_src = (const float*)d_in[7];
    const float* att_dst = (const float*)d_in[8];
    const float* bias_g  = (const float*)d_in[9];
    const float* W3      = (const float*)d_in[10];
    const float* b3      = (const float*)d_in[11];
    float*       out     = (float*)d_out;

    int E = in_sizes[1] / 2;
    const int SMEM = PIPE * STAGE_BYTES;   // 96KB dynamic

    static int s_attr_done = 0;
    if (!s_attr_done) {
        cudaFuncSetAttribute(tf32_gemm_kernel,
                             cudaFuncAttributeMaxDynamicSharedMemorySize, SMEM);
        s_attr_done = 1;
    }

    // 0) dtype sniff + fused prologue (transposes + round_z + zero_cnt)
    {
        int nwords = 4096;
        if (nwords > in_sizes[1]) nwords = in_sizes[1];
        detect_kernel<<<(nwords / 2 + 255) / 256, 256>>>((const unsigned int*)ei, nwords);
    }
    prologue_kernel<<<10591, 256>>>(W1, W2, Wg, W3, z);

    // CSR build
    count_kernel<<<(E + 255) / 256, 256>>>(ei, E);
    scan_kernel<<<1, 1024>>>();
    scatter_kernel<<<(E + 255) / 256, 256>>>(ei, E);

    // 1) x1 = relu(zr @ W1 + b1) -> g_x1 (rounded)
    tf32_gemm_kernel<<<dim3(HID / 128, (NN + 127) / 128), 256, SMEM>>>(
        nullptr, 5, 6, b1, nullptr, 1, NN, HID, LATENT, 1, 1);
    // 2) x2 = relu(x1 @ W2 + b2) -> g_x2 (rounded)
    tf32_gemm_kernel<<<dim3(HID*HEADS / 128, (NN + 127) / 128), 256, SMEM>>>(
        nullptr, 1, 7, b2, nullptr, 2, NN, HID * HEADS, HID, 1, 1);
    // 3) xp = x2 @ Wg -> g_xp (full fp32)
    tf32_gemm_kernel<<<dim3(FEAT / 128, (NN + 127) / 128), 256, SMEM>>>(
        nullptr, 2, 8, nullptr, nullptr, 3, NN, FEAT, HID * HEADS, 0, 0);
    // 4) attention scores
    att_kernel<<<(NN * HEADS + 255) / 256, 256>>>(att_src, att_dst);
    // 5) GAT aggregate
    agg_kernel<<<(NN * 32 + 255) / 256, 256>>>(bias_g);
    // 6) out = xgat @ W3 + b3 -> d_out
    tf32_gemm_kernel<<<dim3(512 / 128, (NN + 127) / 128), 256, SMEM>>>(
        nullptr, 4, 9, b3, out, 0, NN, 512, FEAT, 0, 0);
}